// round 11
// baseline (speedup 1.0000x reference)
#include <cuda_runtime.h>
#include <cuda_bf16.h>
#include <math.h>
#include <stdint.h>

#define Bz 2
#define Tz 1024
#define Cz 1024
#define Hz 16
#define HDz 64
#define Lz 12
#define Vz 50257
#define VzPad 50304
#define BTz (Bz*Tz)
#define C4z (4*Cz)
#define C3z (3*Cz)

// ---------------- scratch (device globals; no allocation) ----------------
__device__ float g_x[BTz*Cz];                         // residual (fp32)
__device__ float g_qkv[(size_t)BTz*C3z];              // QKV output (fp32, attn input)
__device__ float g_red[BTz];
__device__ float g_bpack[C3z];
__device__ float g_wpack[(size_t)Cz*C3z];             // QKV weights concat (fp32)
__device__ __nv_bfloat16 g_hp [(size_t)BTz*2*Cz];     // LN output [hi K | lo K]
__device__ __nv_bfloat16 g_yp [(size_t)BTz*2*Cz];     // attn output [hi | lo]
__device__ __nv_bfloat16 g_ffp[(size_t)BTz*2*C4z];    // MLP hidden [hi | lo]
// packed weights: row n -> [hi(k=0..K-1) | lo(k=0..K-1)]
__device__ __nv_bfloat16 g_pQKV[(size_t)Lz*C3z*2*Cz];
__device__ __nv_bfloat16 g_pWo [(size_t)Lz*Cz*2*Cz];
__device__ __nv_bfloat16 g_pW1 [(size_t)Lz*C4z*2*Cz];
__device__ __nv_bfloat16 g_pW2 [(size_t)Lz*Cz*2*C4z];
__device__ __nv_bfloat16 g_pHead[(size_t)VzPad*2*Cz];

// ---------------- helpers ----------------
__device__ __forceinline__ unsigned short bfhi(float x) {
    return __bfloat16_as_ushort(__float2bfloat16(x));
}
__device__ __forceinline__ unsigned short bflo(float x) {
    __nv_bfloat16 h = __float2bfloat16(x);
    return __bfloat16_as_ushort(__float2bfloat16(x - __bfloat162float(h)));
}

__device__ __forceinline__ float blockReduceSum(float v) {
    __shared__ float sh[33];
    int lane = threadIdx.x & 31, w = threadIdx.x >> 5;
    #pragma unroll
    for (int o = 16; o; o >>= 1) v += __shfl_down_sync(0xffffffffu, v, o);
    __syncthreads();
    if (lane == 0) sh[w] = v;
    __syncthreads();
    if (threadIdx.x == 0) {
        float s = 0.f;
        int nw = blockDim.x >> 5;
        for (int i = 0; i < nw; i++) s += sh[i];
        sh[32] = s;
    }
    __syncthreads();
    return sh[32];
}

__device__ __forceinline__ float blockReduceMax(float v) {
    __shared__ float sh[33];
    int lane = threadIdx.x & 31, w = threadIdx.x >> 5;
    #pragma unroll
    for (int o = 16; o; o >>= 1) v = fmaxf(v, __shfl_down_sync(0xffffffffu, v, o));
    __syncthreads();
    if (lane == 0) sh[w] = v;
    __syncthreads();
    if (threadIdx.x == 0) {
        float s = -1e30f;
        int nw = blockDim.x >> 5;
        for (int i = 0; i < nw; i++) s = fmaxf(s, sh[i]);
        sh[32] = s;
    }
    __syncthreads();
    return sh[32];
}

// ---------------- embedding ----------------
__global__ void embed_kernel(const int* __restrict__ idx,
                             const float* __restrict__ tok,
                             const float* __restrict__ pos) {
    int r = blockIdx.x;
    int c = threadIdx.x * 4;
    int tokid = idx[r];
    float4 te = *(const float4*)(tok + (size_t)tokid * Cz + c);
    float4 pe = *(const float4*)(pos + (size_t)(r % Tz) * Cz + c);
    float4 o;
    o.x = te.x + pe.x; o.y = te.y + pe.y; o.z = te.z + pe.z; o.w = te.w + pe.w;
    *(float4*)(g_x + (size_t)r * Cz + c) = o;
}

// ---------------- layernorm -> packed A rows [hi C | lo C] ----------------
__global__ void ln_pack_kernel(const float* __restrict__ x,
                               const float* __restrict__ w,
                               const float* __restrict__ b,
                               __nv_bfloat16* __restrict__ outp) {
    int r = blockIdx.x;
    const float* xr = x + (size_t)r * Cz;
    float v[4];
    #pragma unroll
    for (int k = 0; k < 4; k++) v[k] = xr[threadIdx.x + k * 256];
    float s = v[0] + v[1] + v[2] + v[3];
    s = blockReduceSum(s);
    float mu = s * (1.0f / Cz);
    float sq = 0.f;
    #pragma unroll
    for (int k = 0; k < 4; k++) { float d = v[k] - mu; sq += d * d; }
    sq = blockReduceSum(sq);
    float rstd = rsqrtf(sq * (1.0f / Cz) + 1e-5f);
    __nv_bfloat16* orow = outp + (size_t)r * 2 * Cz;
    #pragma unroll
    for (int k = 0; k < 4; k++) {
        int c = threadIdx.x + k * 256;
        float xv = (v[k] - mu) * rstd * w[c] + b[c];
        __nv_bfloat16 hb = __float2bfloat16(xv);
        orow[c] = hb;
        orow[Cz + c] = __float2bfloat16(xv - __bfloat162float(hb));
    }
}

// ---------------- QKV weight/bias concat (fp32) ----------------
__global__ void pack_w_kernel(const float* __restrict__ Wq,
                              const float* __restrict__ Wk,
                              const float* __restrict__ Wv) {
    int which = blockIdx.y;
    const float* src = (which == 0) ? Wq : (which == 1) ? Wk : Wv;
    int k = blockIdx.x;
    int c = threadIdx.x * 4;
    float4 v = *(const float4*)(src + (size_t)k * Cz + c);
    *(float4*)(g_wpack + (size_t)k * C3z + which * Cz + c) = v;
}

__global__ void pack_bias_kernel(const float* __restrict__ bq,
                                 const float* __restrict__ bk,
                                 const float* __restrict__ bv) {
    int which = blockIdx.x;
    const float* src = (which == 0) ? bq : (which == 1) ? bk : bv;
    int c = threadIdx.x * 4;
    float4 v = *(const float4*)(src + c);
    *(float4*)(g_bpack + which * Cz + c) = v;
}

// ---------------- weight pack: W[KxN] -> Bp[n][hi K | lo K] ----------------
// grid(Npad/128, K/64), block 256; SMEM transpose for coalescing both sides.
__global__ void packBhl_kernel(const float* __restrict__ W,
                               __nv_bfloat16* __restrict__ dst,
                               int N, int K) {
    __shared__ float sm[64][129];
    int n0 = blockIdx.x * 128, kg = blockIdx.y;
    int tid = threadIdx.x;
    for (int i = tid; i < 64 * 128; i += 256) {
        int k = i >> 7, n = i & 127;
        int ng = n0 + n;
        sm[k][n] = (ng < N) ? W[(size_t)(kg * 64 + k) * N + ng] : 0.f;
    }
    __syncthreads();
    int n = tid & 127, h = tid >> 7;
    __nv_bfloat16* drow = dst + (size_t)(n0 + n) * (2 * K);
    unsigned short hs[32], ls[32];
    #pragma unroll
    for (int j = 0; j < 32; j++) {
        float x = sm[h * 32 + j][n];
        __nv_bfloat16 hb = __float2bfloat16(x);
        hs[j] = __bfloat16_as_ushort(hb);
        ls[j] = __bfloat16_as_ushort(__float2bfloat16(x - __bfloat162float(hb)));
    }
    uint4* dh = (uint4*)(drow + kg * 64 + h * 32);
    dh[0] = ((const uint4*)hs)[0]; dh[1] = ((const uint4*)hs)[1];
    dh[2] = ((const uint4*)hs)[2]; dh[3] = ((const uint4*)hs)[3];
    uint4* dl = (uint4*)(drow + K + kg * 64 + h * 32);
    dl[0] = ((const uint4*)ls)[0]; dl[1] = ((const uint4*)ls)[1];
    dl[2] = ((const uint4*)ls)[2]; dl[3] = ((const uint4*)ls)[3];
}

// ---------------- mma / ldmatrix primitives ----------------
__device__ __forceinline__ void mma16816(float4& c, uint32_t a0, uint32_t a1,
                                         uint32_t a2, uint32_t a3,
                                         uint32_t b0, uint32_t b1) {
    asm volatile(
        "mma.sync.aligned.m16n8k16.row.col.f32.bf16.bf16.f32 "
        "{%0,%1,%2,%3}, {%4,%5,%6,%7}, {%8,%9}, {%0,%1,%2,%3};"
        : "+f"(c.x), "+f"(c.y), "+f"(c.z), "+f"(c.w)
        : "r"(a0), "r"(a1), "r"(a2), "r"(a3), "r"(b0), "r"(b1));
}

__device__ __forceinline__ void ldsm4(uint32_t& r0, uint32_t& r1,
                                      uint32_t& r2, uint32_t& r3, uint32_t addr) {
    asm volatile("ldmatrix.sync.aligned.m8n8.x4.shared.b16 {%0,%1,%2,%3}, [%4];"
        : "=r"(r0), "=r"(r1), "=r"(r2), "=r"(r3) : "r"(addr));
}

// =========================================================================
// GEMM, both sides packed [hi|lo]; 3-stage cp.async ring (race-free).
// A SMEM [128 x (ah32|al32)], B SMEM [128n x (bh32|bl32)], stride 72 bf16.
// 3 fragment-reuse MMA passes per kstep.
// EPI: 0=bias->f32, 1=bias+res->f32, 2=bias+gelu->packed[hi|lo], 3=plain->f32
// =========================================================================
#define AST 72
#define ATILEB (128*AST*2)        // 18432 B per side per stage
#define BUFSZ (2*ATILEB)          // 36864 B per stage
#define GSMEM (3*BUFSZ)           // 110592 B

#define CPA(dst, src) asm volatile("cp.async.cg.shared.global [%0], [%1], 16;\n" :: "r"(dst), "l"(src))

template<int EPI, bool NGUARD>
__global__ void __launch_bounds__(256, 1)
gemm_pk_kernel(const __nv_bfloat16* __restrict__ Apack,
               const __nv_bfloat16* __restrict__ Bpack,
               const float* __restrict__ bias, const float* __restrict__ res,
               float* __restrict__ outF, __nv_bfloat16* __restrict__ outP,
               int N, int K) {
    extern __shared__ __nv_bfloat16 smem[];
    int tid = threadIdx.x, lane = tid & 31, warp = tid >> 5;
    int wm = warp & 1, wn = warp >> 1;
    int g = lane >> 2, tg = lane & 3;
    int rowBlk = blockIdx.y * 128, colBlk = blockIdx.x * 128;
    int row2 = tid >> 1, h2 = tid & 1;          // staging: 128 rows x {hi,lo}
    int t8 = lane >> 3, r8 = lane & 7;
    int aoff = ((t8 & 1) * 8 + r8) * AST + (t8 >> 1) * 8;
    int boff = ((t8 >> 1) * 8 + r8) * AST + (t8 & 1) * 8;
    uint32_t sbase = (uint32_t)__cvta_generic_to_shared(smem);

    const __nv_bfloat16* aRow = Apack + (size_t)(rowBlk + row2) * (2 * K) + (size_t)h2 * K;
    const __nv_bfloat16* bRow = Bpack + (size_t)(colBlk + row2) * (2 * K) + (size_t)h2 * K;

    float4 acc[4][4];
    #pragma unroll
    for (int i = 0; i < 4; i++)
        #pragma unroll
        for (int j = 0; j < 4; j++) acc[i][j] = make_float4(0.f, 0.f, 0.f, 0.f);

#define PREF(bb, kt) { \
        uint32_t ad_ = sbase + (bb) * BUFSZ + (uint32_t)(row2 * AST + h2 * 32) * 2; \
        const __nv_bfloat16* sA_ = aRow + (kt) * 32; \
        CPA(ad_, sA_); CPA(ad_ + 16, sA_ + 8); CPA(ad_ + 32, sA_ + 16); CPA(ad_ + 48, sA_ + 24); \
        uint32_t bd_ = ad_ + ATILEB; \
        const __nv_bfloat16* sB_ = bRow + (kt) * 32; \
        CPA(bd_, sB_); CPA(bd_ + 16, sB_ + 8); CPA(bd_ + 32, sB_ + 16); CPA(bd_ + 48, sB_ + 24); \
        asm volatile("cp.async.commit_group;\n"); }

#define MMAS(bb) { uint32_t Ab = sbase + (bb) * BUFSZ; \
        uint32_t Bb = Ab + ATILEB; \
        _Pragma("unroll") \
        for (int kh = 0; kh < 2; kh++) { \
            int kbh = kh * 16; \
            uint32_t ah[4][4], al[4][4], rbh[4][2], rbl[4][2]; \
            _Pragma("unroll") \
            for (int mf = 0; mf < 4; mf++) { \
                ldsm4(ah[mf][0], ah[mf][1], ah[mf][2], ah[mf][3], \
                      Ab + 2u * (uint32_t)((wm * 64 + mf * 16) * AST + aoff + kbh)); \
                ldsm4(al[mf][0], al[mf][1], al[mf][2], al[mf][3], \
                      Ab + 2u * (uint32_t)((wm * 64 + mf * 16) * AST + aoff + 32 + kbh)); } \
            _Pragma("unroll") \
            for (int p = 0; p < 2; p++) { \
                ldsm4(rbh[2*p][0], rbh[2*p][1], rbh[2*p+1][0], rbh[2*p+1][1], \
                      Bb + 2u * (uint32_t)((wn * 32 + p * 16) * AST + boff + kbh)); \
                ldsm4(rbl[2*p][0], rbl[2*p][1], rbl[2*p+1][0], rbl[2*p+1][1], \
                      Bb + 2u * (uint32_t)((wn * 32 + p * 16) * AST + boff + 32 + kbh)); } \
            _Pragma("unroll") \
            for (int mf = 0; mf < 4; mf++) \
                _Pragma("unroll") \
                for (int nf = 0; nf < 4; nf++) { \
                    mma16816(acc[mf][nf], ah[mf][0], ah[mf][1], ah[mf][2], ah[mf][3], \
                             rbh[nf][0], rbh[nf][1]); \
                    mma16816(acc[mf][nf], al[mf][0], al[mf][1], al[mf][2], al[mf][3], \
                             rbh[nf][0], rbh[nf][1]); \
                    mma16816(acc[mf][nf], ah[mf][0], ah[mf][1], ah[mf][2], ah[mf][3], \
                             rbl[nf][0], rbl[nf][1]); } } }

    int nt = K / 32;
    PREF(0, 0);
    if (nt > 1) PREF(1, 1);
    for (int kt = 0; kt < nt; kt++) {
        int cur = kt % 3;
        if (kt + 1 < nt) {
            asm volatile("cp.async.wait_group 1;\n" ::: "memory");
        } else {
            asm volatile("cp.async.wait_group 0;\n" ::: "memory");
        }
        __syncthreads();
        if (kt + 2 < nt) {
            int nxt = (kt + 2) % 3;
            PREF(nxt, kt + 2);
        }
        MMAS(cur);
    }

    // ---- epilogue ----
    #pragma unroll
    for (int mf = 0; mf < 4; mf++) {
        int row0 = rowBlk + wm * 64 + mf * 16 + g;
        #pragma unroll
        for (int nf = 0; nf < 4; nf++) {
            int col = colBlk + wn * 32 + nf * 8 + tg * 2;
            float vals[4] = {acc[mf][nf].x, acc[mf][nf].y, acc[mf][nf].z, acc[mf][nf].w};
            #pragma unroll
            for (int h = 0; h < 2; h++) {
                int row = row0 + h * 8;
                float v0 = vals[h * 2], v1 = vals[h * 2 + 1];
                if (EPI == 0 || EPI == 1 || EPI == 2) {
                    v0 += bias[col]; v1 += bias[col + 1];
                }
                if (EPI == 2) {
                    v0 = 0.5f * v0 * (1.0f + erff(v0 * 0.7071067811865476f));
                    v1 = 0.5f * v1 * (1.0f + erff(v1 * 0.7071067811865476f));
                }
                if (EPI == 1) {
                    v0 += res[(size_t)row * N + col];
                    v1 += res[(size_t)row * N + col + 1];
                }
                if (EPI == 2) {
                    size_t rowb = (size_t)row * (size_t)(2 * N);
                    *(uint32_t*)(outP + rowb + col) =
                        (uint32_t)bfhi(v0) | ((uint32_t)bfhi(v1) << 16);
                    *(uint32_t*)(outP + rowb + N + col) =
                        (uint32_t)bflo(v0) | ((uint32_t)bflo(v1) << 16);
                } else {
                    if (!NGUARD || col < N)     outF[(size_t)row * N + col] = v0;
                    if (!NGUARD || col + 1 < N) outF[(size_t)row * N + col + 1] = v1;
                }
            }
        }
    }
#undef PREF
#undef MMAS
}

// =========================================================================
// Fused flash attention (epilogue writes g_yp [hi C | lo C])
// =========================================================================
#define FA_QST 200
#define FA_KST 200
#define FA_VST 136
#define FA_SMEM ((64*FA_QST + 64*FA_KST + 64*FA_VST)*2)

__global__ void __launch_bounds__(128, 2)
attn_fused_kernel() {
    extern __shared__ __nv_bfloat16 sm[];
    __nv_bfloat16* Qs = sm;
    __nv_bfloat16* Ks = sm + 64 * FA_QST;
    __nv_bfloat16* Vs = sm + 64 * (FA_QST + FA_KST);
    int tid = threadIdx.x, lane = tid & 31, warp = tid >> 5;
    int qt = blockIdx.x, bh = blockIdx.y;
    int b = bh >> 4, h = bh & 15;
    int g = lane >> 2, tg = lane & 3;
    int t8 = lane >> 3, r8 = lane & 7;
    uint32_t sbb = (uint32_t)__cvta_generic_to_shared(sm);
    uint32_t Qb = sbb;
    uint32_t Kb = sbb + 64 * FA_QST * 2;
    uint32_t Vb = sbb + 64 * (FA_QST + FA_KST) * 2;
    int aoff = ((t8 & 1) * 8 + r8) * FA_QST + (t8 >> 1) * 8;
    int koff = ((t8 >> 1) * 8 + r8) * FA_KST + (t8 & 1) * 8;
    int voff = ((t8 >> 1) * 8 + r8) * FA_VST + (t8 & 1) * 8;

    {
        int row = tid >> 1, seg = (tid & 1) * 32;
        const float* src = g_qkv + (size_t)(b * Tz + qt * 64 + row) * C3z + h * HDz + seg;
        uint32_t wbuf[32]; unsigned short hsb[32];
        #pragma unroll
        for (int i = 0; i < 8; i++) {
            float4 v = *(const float4*)(src + i * 4);
            float xs[4] = {v.x, v.y, v.z, v.w};
            #pragma unroll
            for (int e = 0; e < 4; e++) {
                float x = xs[e] * 0.125f;
                __nv_bfloat16 hb = __float2bfloat16(x);
                __nv_bfloat16 lb = __float2bfloat16(x - __bfloat162float(hb));
                int i4 = i * 4 + e;
                wbuf[i4] = (uint32_t)__bfloat16_as_ushort(hb) |
                           ((uint32_t)__bfloat16_as_ushort(lb) << 16);
                hsb[i4] = __bfloat16_as_ushort(hb);
            }
        }
        uint4* d0 = (uint4*)(Qs + row * FA_QST + 2 * seg);
        #pragma unroll
        for (int i = 0; i < 8; i++) d0[i] = ((const uint4*)wbuf)[i];
        uint32_t hw[16];
        #pragma unroll
        for (int j = 0; j < 16; j++)
            hw[j] = (uint32_t)hsb[2 * j] | ((uint32_t)hsb[2 * j + 1] << 16);
        uint4* d1 = (uint4*)(Qs + row * FA_QST + 128 + seg);
        #pragma unroll
        for (int i = 0; i < 4; i++) d1[i] = ((const uint4*)hw)[i];
    }

    float m0 = -1e30f, m1 = -1e30f, l0 = 0.f, l1 = 0.f;
    float4 O[8];
    #pragma unroll
    for (int i = 0; i < 8; i++) O[i] = make_float4(0.f, 0.f, 0.f, 0.f);

    for (int kt = 0; kt <= qt; kt++) {
        {
            int row = tid >> 1, seg = (tid & 1) * 32;
            const float* src = g_qkv + (size_t)(b * Tz + kt * 64 + row) * C3z + Cz + h * HDz + seg;
            uint32_t wbuf[32]; unsigned short lsb[32];
            #pragma unroll
            for (int i = 0; i < 8; i++) {
                float4 v = *(const float4*)(src + i * 4);
                float xs[4] = {v.x, v.y, v.z, v.w};
                #pragma unroll
                for (int e = 0; e < 4; e++) {
                    float x = xs[e];
                    __nv_bfloat16 hb = __float2bfloat16(x);
                    unsigned short hu = __bfloat16_as_ushort(hb);
                    __nv_bfloat16 lb = __float2bfloat16(x - __bfloat162float(hb));
                    int i4 = i * 4 + e;
                    wbuf[i4] = (uint32_t)hu | ((uint32_t)hu << 16);
                    lsb[i4] = __bfloat16_as_ushort(lb);
                }
            }
            uint4* d0 = (uint4*)(Ks + row * FA_KST + 2 * seg);
            #pragma unroll
            for (int i = 0; i < 8; i++) d0[i] = ((const uint4*)wbuf)[i];
            uint32_t lw[16];
            #pragma unroll
            for (int j = 0; j < 16; j++)
                lw[j] = (uint32_t)lsb[2 * j] | ((uint32_t)lsb[2 * j + 1] << 16);
            uint4* d1 = (uint4*)(Ks + row * FA_KST + 128 + seg);
            #pragma unroll
            for (int i = 0; i < 4; i++) d1[i] = ((const uint4*)lw)[i];
        }
        {
            int nd = (tid & 15) * 4;
            int k8 = (tid >> 4) * 8;
            unsigned short vh[4][8], vl[4][8];
            #pragma unroll
            for (int kk = 0; kk < 8; kk++) {
                const float* src = g_qkv + (size_t)(b * Tz + kt * 64 + k8 + kk) * C3z + 2 * Cz + h * HDz + nd;
                float4 v = *(const float4*)src;
                float xs[4] = {v.x, v.y, v.z, v.w};
                #pragma unroll
                for (int e = 0; e < 4; e++) {
                    float x = xs[e];
                    __nv_bfloat16 hb = __float2bfloat16(x);
                    __nv_bfloat16 lb = __float2bfloat16(x - __bfloat162float(hb));
                    vh[e][kk] = __bfloat16_as_ushort(hb);
                    vl[e][kk] = __bfloat16_as_ushort(lb);
                }
            }
            #pragma unroll
            for (int e = 0; e < 4; e++) {
                *(uint4*)(Vs + (nd + e) * FA_VST + k8)      = *(const uint4*)vh[e];
                *(uint4*)(Vs + (nd + e) * FA_VST + 64 + k8) = *(const uint4*)vl[e];
            }
        }
        __syncthreads();

        float4 S[8];
        #pragma unroll
        for (int i = 0; i < 8; i++) S[i] = make_float4(0.f, 0.f, 0.f, 0.f);
        #pragma unroll
        for (int ks = 0; ks < 12; ks++) {
            int kb = ks * 16;
            uint32_t ra0, ra1, ra2, ra3;
            ldsm4(ra0, ra1, ra2, ra3, Qb + 2u * (uint32_t)(warp * 16 * FA_QST + aoff + kb));
            #pragma unroll
            for (int pp = 0; pp < 4; pp++) {
                uint32_t b0, b1, b2, b3;
                ldsm4(b0, b1, b2, b3, Kb + 2u * (uint32_t)((pp * 16) * FA_KST + koff + kb));
                mma16816(S[2 * pp],     ra0, ra1, ra2, ra3, b0, b1);
                mma16816(S[2 * pp + 1], ra0, ra1, ra2, ra3, b2, b3);
            }
        }

        if (kt == qt) {
            int r0 = warp * 16 + g, r1 = r0 + 8;
            #pragma unroll
            for (int j = 0; j < 8; j++) {
                int c0 = j * 8 + 2 * tg, c1 = c0 + 1;
                if (c0 > r0) S[j].x = -1e30f;
                if (c1 > r0) S[j].y = -1e30f;
                if (c0 > r1) S[j].z = -1e30f;
                if (c1 > r1) S[j].w = -1e30f;
            }
        }

        float mx0 = -1e30f, mx1 = -1e30f;
        #pragma unroll
        for (int j = 0; j < 8; j++) {
            mx0 = fmaxf(mx0, fmaxf(S[j].x, S[j].y));
            mx1 = fmaxf(mx1, fmaxf(S[j].z, S[j].w));
        }
        mx0 = fmaxf(mx0, __shfl_xor_sync(0xffffffffu, mx0, 1));
        mx0 = fmaxf(mx0, __shfl_xor_sync(0xffffffffu, mx0, 2));
        mx1 = fmaxf(mx1, __shfl_xor_sync(0xffffffffu, mx1, 1));
        mx1 = fmaxf(mx1, __shfl_xor_sync(0xffffffffu, mx1, 2));
        float mn0 = fmaxf(m0, mx0), mn1 = fmaxf(m1, mx1);
        float al0 = __expf(m0 - mn0), al1 = __expf(m1 - mn1);
        m0 = mn0; m1 = mn1;
        float rs0 = 0.f, rs1 = 0.f;
        #pragma unroll
        for (int j = 0; j < 8; j++) {
            S[j].x = __expf(S[j].x - m0);
            S[j].y = __expf(S[j].y - m0);
            S[j].z = __expf(S[j].z - m1);
            S[j].w = __expf(S[j].w - m1);
            rs0 += S[j].x + S[j].y;
            rs1 += S[j].z + S[j].w;
        }
        rs0 += __shfl_xor_sync(0xffffffffu, rs0, 1);
        rs0 += __shfl_xor_sync(0xffffffffu, rs0, 2);
        rs1 += __shfl_xor_sync(0xffffffffu, rs1, 1);
        rs1 += __shfl_xor_sync(0xffffffffu, rs1, 2);
        l0 = l0 * al0 + rs0;
        l1 = l1 * al1 + rs1;
        #pragma unroll
        for (int j = 0; j < 8; j++) {
            O[j].x *= al0; O[j].y *= al0;
            O[j].z *= al1; O[j].w *= al1;
        }

        #pragma unroll
        for (int kc = 0; kc < 4; kc++) {
            float4 s0 = S[2 * kc], s1 = S[2 * kc + 1];
            float f0[8] = {s0.x, s0.y, s0.z, s0.w, s1.x, s1.y, s1.z, s1.w};
            unsigned short phs[8], pls[8];
            #pragma unroll
            for (int e = 0; e < 8; e++) {
                __nv_bfloat16 hb = __float2bfloat16(f0[e]);
                phs[e] = __bfloat16_as_ushort(hb);
                pls[e] = __bfloat16_as_ushort(__float2bfloat16(f0[e] - __bfloat162float(hb)));
            }
            uint32_t ph0 = (uint32_t)phs[0] | ((uint32_t)phs[1] << 16);
            uint32_t ph1 = (uint32_t)phs[2] | ((uint32_t)phs[3] << 16);
            uint32_t ph2 = (uint32_t)phs[4] | ((uint32_t)phs[5] << 16);
            uint32_t ph3 = (uint32_t)phs[6] | ((uint32_t)phs[7] << 16);
            uint32_t pl0 = (uint32_t)pls[0] | ((uint32_t)pls[1] << 16);
            uint32_t pl1 = (uint32_t)pls[2] | ((uint32_t)pls[3] << 16);
            uint32_t pl2 = (uint32_t)pls[4] | ((uint32_t)pls[5] << 16);
            uint32_t pl3 = (uint32_t)pls[6] | ((uint32_t)pls[7] << 16);

            uint32_t vh[8][2], vl[8][2];
            #pragma unroll
            for (int pp = 0; pp < 4; pp++) {
                ldsm4(vh[2*pp][0], vh[2*pp][1], vh[2*pp+1][0], vh[2*pp+1][1],
                      Vb + 2u * (uint32_t)((pp * 16) * FA_VST + voff + kc * 16));
                ldsm4(vl[2*pp][0], vl[2*pp][1], vl[2*pp+1][0], vl[2*pp+1][1],
                      Vb + 2u * (uint32_t)((pp * 16) * FA_VST + voff + 64 + kc * 16));
            }
            #pragma unroll
            for (int nf = 0; nf < 8; nf++) {
                mma16816(O[nf], ph0, ph1, ph2, ph3, vh[nf][0], vh[nf][1]);
                mma16816(O[nf], pl0, pl1, pl2, pl3, vh[nf][0], vh[nf][1]);
                mma16816(O[nf], ph0, ph1, ph2, ph3, vl[nf][0], vl[nf][1]);
            }
        }
        __syncthreads();
    }

    float i0 = 1.0f / l0, i1 = 1.0f / l1;
    int qrow = qt * 64 + warp * 16 + g;
    size_t rb0 = (size_t)(b * Tz + qrow) * (2 * Cz);
    size_t rb1 = (size_t)(b * Tz + qrow + 8) * (2 * Cz);
    #pragma unroll
    for (int nf = 0; nf < 8; nf++) {
        int colg = h * HDz + nf * 8 + 2 * tg;
        float vx = O[nf].x * i0, vy = O[nf].y * i0;
        float wx = O[nf].z * i1, wy = O[nf].w * i1;
        *(uint32_t*)(g_yp + rb0 + colg)      = (uint32_t)bfhi(vx) | ((uint32_t)bfhi(vy) << 16);
        *(uint32_t*)(g_yp + rb0 + Cz + colg) = (uint32_t)bflo(vx) | ((uint32_t)bflo(vy) << 16);
        *(uint32_t*)(g_yp + rb1 + colg)      = (uint32_t)bfhi(wx) | ((uint32_t)bfhi(wy) << 16);
        *(uint32_t*)(g_yp + rb1 + Cz + colg) = (uint32_t)bflo(wx) | ((uint32_t)bflo(wy) << 16);
    }
}

// ---------------- loss ----------------
__global__ void loss_row_kernel(const float* __restrict__ logits,
                                const int* __restrict__ targets) {
    int r = blockIdx.x;
    const float* row = logits + (size_t)r * Vz;
    int tid = threadIdx.x;
    float mx = -1e30f;
    for (int j = tid; j < Vz; j += 256) mx = fmaxf(mx, row[j]);
    mx = blockReduceMax(mx);
    float s = 0.f;
    for (int j = tid; j < Vz; j += 256) s += expf(row[j] - mx);
    s = blockReduceSum(s);
    if (tid == 0) {
        int t = targets[r];
        g_red[r] = -(row[t] - mx - logf(s));
    }
}

__global__ void loss_final_kernel(float* __restrict__ out, int out_size) {
    int tid = threadIdx.x;
    float s = 0.f;
    for (int j = tid; j < BTz; j += 256) s += g_red[j];
    s = blockReduceSum(s);
    if (tid == 0) {
        long long logits_elems = (long long)BTz * Vz;
        if ((long long)out_size > logits_elems)
            out[logits_elems] = s / (float)BTz;
    }
}

// ---------------- launch ----------------
extern "C" void kernel_launch(void* const* d_in, const int* in_sizes, int n_in,
                              void* d_out, int out_size) {
    const int*   idx     = (const int*)d_in[0];
    const int*   targets = (const int*)d_in[1];
    const float* tok_emb = (const float*)d_in[2];
    const float* pos_emb = (const float*)d_in[3];
    const float* ln1_w   = (const float*)d_in[4];
    const float* ln1_b   = (const float*)d_in[5];
    const float* ln2_w   = (const float*)d_in[6];
    const float* ln2_b   = (const float*)d_in[7];
    const float* Wq = (const float*)d_in[8];
    const float* bq = (const float*)d_in[9];
    const float* Wk = (const float*)d_in[10];
    const float* bk = (const float*)d_in[11];
    const float* Wv = (const float*)d_in[12];
    const float* bv = (const float*)d_in[13];
    const float* Wo = (const float*)d_in[14];
    const float* bo = (const float*)d_in[15];
    const float* W1 = (const float*)d_in[16];
    const float* b1 = (const float*)d_in[17];
    const float* W2 = (const float*)d_in[18];
    const float* b2 = (const float*)d_in[19];
    const float* lnf_w  = (const float*)d_in[20];
    const float* lnf_b  = (const float*)d_in[21];
    const float* head_w = (const float*)d_in[22];
    float* out = (float*)d_out;

    float *px, *pbp, *pwp, *pqkv;
    __nv_bfloat16 *php, *pffp, *pyp, *pQ, *pO, *p1, *p2, *pH;
    cudaGetSymbolAddress((void**)&px,   g_x);
    cudaGetSymbolAddress((void**)&pbp,  g_bpack);
    cudaGetSymbolAddress((void**)&pwp,  g_wpack);
    cudaGetSymbolAddress((void**)&pqkv, g_qkv);
    cudaGetSymbolAddress((void**)&php,  g_hp);
    cudaGetSymbolAddress((void**)&pffp, g_ffp);
    cudaGetSymbolAddress((void**)&pyp,  g_yp);
    cudaGetSymbolAddress((void**)&pQ,   g_pQKV);
    cudaGetSymbolAddress((void**)&pO,   g_pWo);
    cudaGetSymbolAddress((void**)&p1,   g_pW1);
    cudaGetSymbolAddress((void**)&p2,   g_pW2);
    cudaGetSymbolAddress((void**)&pH,   g_pHead);

    cudaFuncSetAttribute(gemm_pk_kernel<0, false>, cudaFuncAttributeMaxDynamicSharedMemorySize, GSMEM);
    cudaFuncSetAttribute(gemm_pk_kernel<1, false>, cudaFuncAttributeMaxDynamicSharedMemorySize, GSMEM);
    cudaFuncSetAttribute(gemm_pk_kernel<2, false>, cudaFuncAttributeMaxDynamicSharedMemorySize, GSMEM);
    cudaFuncSetAttribute(gemm_pk_kernel<3, true >, cudaFuncAttributeMaxDynamicSharedMemorySize, GSMEM);
    cudaFuncSetAttribute(attn_fused_kernel, cudaFuncAttributeMaxDynamicSharedMemorySize, FA_SMEM);

    const size_t CC  = (size_t)Cz * Cz;
    const size_t C14 = (size_t)Cz * C4z;

    // ---- pre-pack all weights into [hi K | lo K] rows ----
    for (int l = 0; l < Lz; l++) {
        pack_w_kernel<<<dim3(Cz, 3), 256>>>(Wq + l * CC, Wk + l * CC, Wv + l * CC);
        packBhl_kernel<<<dim3(24, 16), 256>>>(pwp, pQ + (size_t)l * C3z * 2 * Cz, C3z, Cz);
        packBhl_kernel<<<dim3(8, 16), 256>>>(Wo + l * CC, pO + (size_t)l * Cz * 2 * Cz, Cz, Cz);
        packBhl_kernel<<<dim3(32, 16), 256>>>(W1 + l * C14, p1 + (size_t)l * C4z * 2 * Cz, C4z, Cz);
        packBhl_kernel<<<dim3(8, 64), 256>>>(W2 + l * C14, p2 + (size_t)l * Cz * 2 * C4z, Cz, C4z);
    }
    packBhl_kernel<<<dim3(VzPad / 128, 16), 256>>>(head_w, pH, Vz, Cz);

    embed_kernel<<<BTz, 256>>>(idx, tok_emb, pos_emb);

    dim3 gQKV(24, 16), gCC(8, 16), gC4(32, 16), gHead(VzPad / 128, 16);

    for (int l = 0; l < Lz; l++) {
        pack_bias_kernel<<<3, 256>>>(bq + (size_t)l * Cz, bk + (size_t)l * Cz, bv + (size_t)l * Cz);
        ln_pack_kernel<<<BTz, 256>>>(px, ln1_w + (size_t)l * Cz, ln1_b + (size_t)l * Cz, php);
        gemm_pk_kernel<0, false><<<gQKV, 256, GSMEM>>>(php, pQ + (size_t)l * C3z * 2 * Cz,
                                                       pbp, nullptr, pqkv, nullptr, C3z, Cz);
        attn_fused_kernel<<<dim3(Tz / 64, Bz * Hz), 128, FA_SMEM>>>();
        gemm_pk_kernel<1, false><<<gCC, 256, GSMEM>>>(pyp, pO + (size_t)l * Cz * 2 * Cz,
                                                      bo + (size_t)l * Cz, px, px, nullptr, Cz, Cz);
        ln_pack_kernel<<<BTz, 256>>>(px, ln2_w + (size_t)l * Cz, ln2_b + (size_t)l * Cz, php);
        gemm_pk_kernel<2, false><<<gC4, 256, GSMEM>>>(php, p1 + (size_t)l * C4z * 2 * Cz,
                                                      b1 + (size_t)l * C4z, nullptr, nullptr, pffp, C4z, Cz);
        gemm_pk_kernel<1, false><<<gCC, 256, GSMEM>>>(pffp, p2 + (size_t)l * Cz * 2 * C4z,
                                                      b2 + (size_t)l * Cz, px, px, nullptr, Cz, C4z);
    }

    ln_pack_kernel<<<BTz, 256>>>(px, lnf_w, lnf_b, php);
    gemm_pk_kernel<3, true><<<gHead, 256, GSMEM>>>(php, pH, nullptr, nullptr, out, nullptr, Vz, Cz);
    loss_row_kernel<<<BTz, 256>>>(out, targets);
    loss_final_kernel<<<1, 256>>>(out, out_size);
}

// round 14
// speedup vs baseline: 1.0688x; 1.0688x over previous
#include <cuda_runtime.h>
#include <cuda_bf16.h>
#include <math.h>
#include <stdint.h>

#define Bz 2
#define Tz 1024
#define Cz 1024
#define Hz 16
#define HDz 64
#define Lz 12
#define Vz 50257
#define BTz (Bz*Tz)
#define C4z (4*Cz)
#define C3z (3*Cz)

// ---------------- scratch (device globals; no allocation) ----------------
__device__ float g_x[BTz*Cz];                         // residual (fp32)
__device__ float g_qkv[(size_t)BTz*C3z];              // QKV output (fp32, attn input)
__device__ float g_red[BTz];
__device__ float g_bpack[C3z];
__device__ float g_wpack[(size_t)Cz*C3z];             // QKV weights concat (fp32)
__device__ __nv_bfloat16 g_hp [(size_t)BTz*2*Cz];     // LN output [hi K | lo K]
__device__ __nv_bfloat16 g_yp [(size_t)BTz*2*Cz];     // attn output [hi | lo]
__device__ __nv_bfloat16 g_ffp[(size_t)BTz*2*C4z];    // MLP hidden [hi | lo]

// ---------------- helpers ----------------
__device__ __forceinline__ unsigned short bfhi(float x) {
    return __bfloat16_as_ushort(__float2bfloat16(x));
}
__device__ __forceinline__ unsigned short bflo(float x) {
    __nv_bfloat16 h = __float2bfloat16(x);
    return __bfloat16_as_ushort(__float2bfloat16(x - __bfloat162float(h)));
}

__device__ __forceinline__ float blockReduceSum(float v) {
    __shared__ float sh[33];
    int lane = threadIdx.x & 31, w = threadIdx.x >> 5;
    #pragma unroll
    for (int o = 16; o; o >>= 1) v += __shfl_down_sync(0xffffffffu, v, o);
    __syncthreads();
    if (lane == 0) sh[w] = v;
    __syncthreads();
    if (threadIdx.x == 0) {
        float s = 0.f;
        int nw = blockDim.x >> 5;
        for (int i = 0; i < nw; i++) s += sh[i];
        sh[32] = s;
    }
    __syncthreads();
    return sh[32];
}

__device__ __forceinline__ float blockReduceMax(float v) {
    __shared__ float sh[33];
    int lane = threadIdx.x & 31, w = threadIdx.x >> 5;
    #pragma unroll
    for (int o = 16; o; o >>= 1) v = fmaxf(v, __shfl_down_sync(0xffffffffu, v, o));
    __syncthreads();
    if (lane == 0) sh[w] = v;
    __syncthreads();
    if (threadIdx.x == 0) {
        float s = -1e30f;
        int nw = blockDim.x >> 5;
        for (int i = 0; i < nw; i++) s = fmaxf(s, sh[i]);
        sh[32] = s;
    }
    __syncthreads();
    return sh[32];
}

// ---------------- embedding ----------------
__global__ void embed_kernel(const int* __restrict__ idx,
                             const float* __restrict__ tok,
                             const float* __restrict__ pos) {
    int r = blockIdx.x;
    int c = threadIdx.x * 4;
    int tokid = idx[r];
    float4 te = *(const float4*)(tok + (size_t)tokid * Cz + c);
    float4 pe = *(const float4*)(pos + (size_t)(r % Tz) * Cz + c);
    float4 o;
    o.x = te.x + pe.x; o.y = te.y + pe.y; o.z = te.z + pe.z; o.w = te.w + pe.w;
    *(float4*)(g_x + (size_t)r * Cz + c) = o;
}

// ---------------- layernorm -> packed A rows [hi C | lo C] ----------------
__global__ void ln_pack_kernel(const float* __restrict__ x,
                               const float* __restrict__ w,
                               const float* __restrict__ b,
                               __nv_bfloat16* __restrict__ outp) {
    int r = blockIdx.x;
    const float* xr = x + (size_t)r * Cz;
    float v[4];
    #pragma unroll
    for (int k = 0; k < 4; k++) v[k] = xr[threadIdx.x + k * 256];
    float s = v[0] + v[1] + v[2] + v[3];
    s = blockReduceSum(s);
    float mu = s * (1.0f / Cz);
    float sq = 0.f;
    #pragma unroll
    for (int k = 0; k < 4; k++) { float d = v[k] - mu; sq += d * d; }
    sq = blockReduceSum(sq);
    float rstd = rsqrtf(sq * (1.0f / Cz) + 1e-5f);
    __nv_bfloat16* orow = outp + (size_t)r * 2 * Cz;
    #pragma unroll
    for (int k = 0; k < 4; k++) {
        int c = threadIdx.x + k * 256;
        float xv = (v[k] - mu) * rstd * w[c] + b[c];
        __nv_bfloat16 hb = __float2bfloat16(xv);
        orow[c] = hb;
        orow[Cz + c] = __float2bfloat16(xv - __bfloat162float(hb));
    }
}

// ---------------- QKV weight/bias concat (fp32) ----------------
__global__ void pack_w_kernel(const float* __restrict__ Wq,
                              const float* __restrict__ Wk,
                              const float* __restrict__ Wv) {
    int which = blockIdx.y;
    const float* src = (which == 0) ? Wq : (which == 1) ? Wk : Wv;
    int k = blockIdx.x;
    int c = threadIdx.x * 4;
    float4 v = *(const float4*)(src + (size_t)k * Cz + c);
    *(float4*)(g_wpack + (size_t)k * C3z + which * Cz + c) = v;
}

__global__ void pack_bias_kernel(const float* __restrict__ bq,
                                 const float* __restrict__ bk,
                                 const float* __restrict__ bv) {
    int which = blockIdx.x;
    const float* src = (which == 0) ? bq : (which == 1) ? bk : bv;
    int c = threadIdx.x * 4;
    float4 v = *(const float4*)(src + c);
    *(float4*)(g_bpack + which * Cz + c) = v;
}

// ---------------- mma / ldmatrix primitives ----------------
__device__ __forceinline__ void mma16816(float4& c, uint32_t a0, uint32_t a1,
                                         uint32_t a2, uint32_t a3,
                                         uint32_t b0, uint32_t b1) {
    asm volatile(
        "mma.sync.aligned.m16n8k16.row.col.f32.bf16.bf16.f32 "
        "{%0,%1,%2,%3}, {%4,%5,%6,%7}, {%8,%9}, {%0,%1,%2,%3};"
        : "+f"(c.x), "+f"(c.y), "+f"(c.z), "+f"(c.w)
        : "r"(a0), "r"(a1), "r"(a2), "r"(a3), "r"(b0), "r"(b1));
}

__device__ __forceinline__ void ldsm4(uint32_t& r0, uint32_t& r1,
                                      uint32_t& r2, uint32_t& r3, uint32_t addr) {
    asm volatile("ldmatrix.sync.aligned.m8n8.x4.shared.b16 {%0,%1,%2,%3}, [%4];"
        : "=r"(r0), "=r"(r1), "=r"(r2), "=r"(r3) : "r"(addr));
}

// =========================================================================
// GEMM, 128x64 tile (2 CTAs/SM), shared-segment hi/lo, 3 MMA passes/kstep.
// RACE-FREE pipeline: PREFA issued AFTER the barrier (WAR hazard closed).
// EPI: 0=bias->f32, 1=bias+res->f32, 2=bias+gelu->packed[hi|lo], 3=plain->f32
// =========================================================================
#define AST 72
#define ATILEB (128*AST*2)        // 18432 B (A side)
#define BTILEB (64*AST*2)         // 9216 B  (B side)
#define BUFSZ (ATILEB+BTILEB)     // 27648 B per stage
#define GSMEM (2*BUFSZ)           // 55296 B -> 2 CTAs/SM

#define CPA(dst, src) asm volatile("cp.async.cg.shared.global [%0], [%1], 16;\n" :: "r"(dst), "l"(src))

template<int EPI, bool NGUARD>
__global__ void __launch_bounds__(256, 2)
gemm_pk_kernel(const __nv_bfloat16* __restrict__ Apack,
               const float* __restrict__ Bm,
               const float* __restrict__ bias, const float* __restrict__ res,
               float* __restrict__ outF, __nv_bfloat16* __restrict__ outP,
               int N, int K) {
    extern __shared__ __nv_bfloat16 smem[];
    int tid = threadIdx.x, lane = tid & 31, warp = tid >> 5;
    int wm = warp & 1, wn = warp >> 1;         // 2 x 4 warps over 128 x 64
    int g = lane >> 2, tg = lane & 3;
    int rowBlk = blockIdx.y * 128, colBlk = blockIdx.x * 64;
    int row2 = tid >> 1, h2 = tid & 1;         // A staging: 128 rows x {hi,lo}
    int bn = tid & 63, part = tid >> 6;        // B staging: 64 cols x 4 k-parts of 8
    int t8 = lane >> 3, r8 = lane & 7;
    int aoff = ((t8 & 1) * 8 + r8) * AST + (t8 >> 1) * 8;
    int boff = ((t8 >> 1) * 8 + r8) * AST + (t8 & 1) * 8;
    uint32_t sbase = (uint32_t)__cvta_generic_to_shared(smem);

    const __nv_bfloat16* aRow = Apack + (size_t)(rowBlk + row2) * (2 * K) + (size_t)h2 * K;
    int nb = colBlk + bn;
    bool bValid = (!NGUARD) || (nb < N);
    const float* bPtr = Bm + (bValid ? nb : 0);

    float fb[8];
    float4 acc[4][2];
    #pragma unroll
    for (int i = 0; i < 4; i++)
        #pragma unroll
        for (int j = 0; j < 2; j++) acc[i][j] = make_float4(0.f, 0.f, 0.f, 0.f);

#define PREFA(s, kt) { \
        uint32_t ad_ = sbase + (s) * BUFSZ + (uint32_t)(row2 * AST + h2 * 32) * 2; \
        const __nv_bfloat16* sA_ = aRow + (kt) * 32; \
        CPA(ad_, sA_); CPA(ad_ + 16, sA_ + 8); CPA(ad_ + 32, sA_ + 16); CPA(ad_ + 48, sA_ + 24); \
        asm volatile("cp.async.commit_group;\n"); }

#define LDGB(kt) { const float* p = bPtr + (size_t)((kt) * 32 + part * 8) * N; \
        _Pragma("unroll") \
        for (int i = 0; i < 8; i++) fb[i] = (!NGUARD || bValid) ? p[(size_t)i * N] : 0.f; }

#define CVTB(s) { \
        unsigned short hs_[8], ls_[8]; \
        _Pragma("unroll") \
        for (int i = 0; i < 8; i++) { \
            float x = fb[i]; \
            __nv_bfloat16 h = __float2bfloat16(x); \
            hs_[i] = __bfloat16_as_ushort(h); \
            ls_[i] = __bfloat16_as_ushort(__float2bfloat16(x - __bfloat162float(h))); } \
        __nv_bfloat16* Bs_ = smem + ((s) * BUFSZ + ATILEB) / 2 + bn * AST; \
        *(uint4*)(Bs_ + part * 8)      = *((const uint4*)hs_); \
        *(uint4*)(Bs_ + 32 + part * 8) = *((const uint4*)ls_); }

#define MMAS(s) { uint32_t Ab = sbase + (s) * BUFSZ; \
        uint32_t Bb = Ab + ATILEB; \
        _Pragma("unroll") \
        for (int kh = 0; kh < 2; kh++) { \
            int kbh = kh * 16; \
            uint32_t ah[4][4], al[4][4], rbh[2][2], rbl[2][2]; \
            _Pragma("unroll") \
            for (int mf = 0; mf < 4; mf++) { \
                ldsm4(ah[mf][0], ah[mf][1], ah[mf][2], ah[mf][3], \
                      Ab + 2u * (uint32_t)((wm * 64 + mf * 16) * AST + aoff + kbh)); \
                ldsm4(al[mf][0], al[mf][1], al[mf][2], al[mf][3], \
                      Ab + 2u * (uint32_t)((wm * 64 + mf * 16) * AST + aoff + 32 + kbh)); } \
            ldsm4(rbh[0][0], rbh[0][1], rbh[1][0], rbh[1][1], \
                  Bb + 2u * (uint32_t)((wn * 16) * AST + boff + kbh)); \
            ldsm4(rbl[0][0], rbl[0][1], rbl[1][0], rbl[1][1], \
                  Bb + 2u * (uint32_t)((wn * 16) * AST + boff + 32 + kbh)); \
            _Pragma("unroll") \
            for (int mf = 0; mf < 4; mf++) \
                _Pragma("unroll") \
                for (int nf = 0; nf < 2; nf++) { \
                    mma16816(acc[mf][nf], ah[mf][0], ah[mf][1], ah[mf][2], ah[mf][3], \
                             rbh[nf][0], rbh[nf][1]); \
                    mma16816(acc[mf][nf], al[mf][0], al[mf][1], al[mf][2], al[mf][3], \
                             rbh[nf][0], rbh[nf][1]); \
                    mma16816(acc[mf][nf], ah[mf][0], ah[mf][1], ah[mf][2], ah[mf][3], \
                             rbl[nf][0], rbl[nf][1]); } } }

    int nt = K / 32;
    // prologue: stage tile 0 (A via cp.async, B via LDG+CVT)
    PREFA(0, 0);
    LDGB(0);
    CVTB(0);
    for (int kt = 0; kt < nt; kt++) {
        int s = kt & 1;
        if (kt + 1 < nt) LDGB(kt + 1);
        asm volatile("cp.async.wait_group 0;\n" ::: "memory");
        __syncthreads();
        // PREFA after the barrier: buffer s^1's last readers (MMAS@kt-1) are done.
        if (kt + 1 < nt) PREFA(s ^ 1, kt + 1);
        MMAS(s);
        if (kt + 1 < nt) CVTB(s ^ 1);
    }

    // ---- epilogue ----
    #pragma unroll
    for (int mf = 0; mf < 4; mf++) {
        int row0 = rowBlk + wm * 64 + mf * 16 + g;
        #pragma unroll
        for (int nf = 0; nf < 2; nf++) {
            int col = colBlk + wn * 16 + nf * 8 + tg * 2;
            float vals[4] = {acc[mf][nf].x, acc[mf][nf].y, acc[mf][nf].z, acc[mf][nf].w};
            #pragma unroll
            for (int h = 0; h < 2; h++) {
                int row = row0 + h * 8;
                float v0 = vals[h * 2], v1 = vals[h * 2 + 1];
                if (EPI == 0 || EPI == 1 || EPI == 2) {
                    v0 += bias[col]; v1 += bias[col + 1];
                }
                if (EPI == 2) {
                    v0 = 0.5f * v0 * (1.0f + erff(v0 * 0.7071067811865476f));
                    v1 = 0.5f * v1 * (1.0f + erff(v1 * 0.7071067811865476f));
                }
                if (EPI == 1) {
                    v0 += res[(size_t)row * N + col];
                    v1 += res[(size_t)row * N + col + 1];
                }
                if (EPI == 2) {
                    size_t rowb = (size_t)row * (size_t)(2 * N);
                    *(uint32_t*)(outP + rowb + col) =
                        (uint32_t)bfhi(v0) | ((uint32_t)bfhi(v1) << 16);
                    *(uint32_t*)(outP + rowb + N + col) =
                        (uint32_t)bflo(v0) | ((uint32_t)bflo(v1) << 16);
                } else {
                    if (!NGUARD || col < N)     outF[(size_t)row * N + col] = v0;
                    if (!NGUARD || col + 1 < N) outF[(size_t)row * N + col + 1] = v1;
                }
            }
        }
    }
#undef PREFA
#undef LDGB
#undef CVTB
#undef MMAS
}

// =========================================================================
// Fused flash attention (epilogue writes g_yp [hi C | lo C])
// =========================================================================
#define FA_QST 200
#define FA_KST 200
#define FA_VST 136
#define FA_SMEM ((64*FA_QST + 64*FA_KST + 64*FA_VST)*2)

__global__ void __launch_bounds__(128, 2)
attn_fused_kernel() {
    extern __shared__ __nv_bfloat16 sm[];
    __nv_bfloat16* Qs = sm;
    __nv_bfloat16* Ks = sm + 64 * FA_QST;
    __nv_bfloat16* Vs = sm + 64 * (FA_QST + FA_KST);
    int tid = threadIdx.x, lane = tid & 31, warp = tid >> 5;
    int qt = blockIdx.x, bh = blockIdx.y;
    int b = bh >> 4, h = bh & 15;
    int g = lane >> 2, tg = lane & 3;
    int t8 = lane >> 3, r8 = lane & 7;
    uint32_t sbb = (uint32_t)__cvta_generic_to_shared(sm);
    uint32_t Qb = sbb;
    uint32_t Kb = sbb + 64 * FA_QST * 2;
    uint32_t Vb = sbb + 64 * (FA_QST + FA_KST) * 2;
    int aoff = ((t8 & 1) * 8 + r8) * FA_QST + (t8 >> 1) * 8;
    int koff = ((t8 >> 1) * 8 + r8) * FA_KST + (t8 & 1) * 8;
    int voff = ((t8 >> 1) * 8 + r8) * FA_VST + (t8 & 1) * 8;

    {
        int row = tid >> 1, seg = (tid & 1) * 32;
        const float* src = g_qkv + (size_t)(b * Tz + qt * 64 + row) * C3z + h * HDz + seg;
        uint32_t wbuf[32]; unsigned short hsb[32];
        #pragma unroll
        for (int i = 0; i < 8; i++) {
            float4 v = *(const float4*)(src + i * 4);
            float xs[4] = {v.x, v.y, v.z, v.w};
            #pragma unroll
            for (int e = 0; e < 4; e++) {
                float x = xs[e] * 0.125f;
                __nv_bfloat16 hb = __float2bfloat16(x);
                __nv_bfloat16 lb = __float2bfloat16(x - __bfloat162float(hb));
                int i4 = i * 4 + e;
                wbuf[i4] = (uint32_t)__bfloat16_as_ushort(hb) |
                           ((uint32_t)__bfloat16_as_ushort(lb) << 16);
                hsb[i4] = __bfloat16_as_ushort(hb);
            }
        }
        uint4* d0 = (uint4*)(Qs + row * FA_QST + 2 * seg);
        #pragma unroll
        for (int i = 0; i < 8; i++) d0[i] = ((const uint4*)wbuf)[i];
        uint32_t hw[16];
        #pragma unroll
        for (int j = 0; j < 16; j++)
            hw[j] = (uint32_t)hsb[2 * j] | ((uint32_t)hsb[2 * j + 1] << 16);
        uint4* d1 = (uint4*)(Qs + row * FA_QST + 128 + seg);
        #pragma unroll
        for (int i = 0; i < 4; i++) d1[i] = ((const uint4*)hw)[i];
    }

    float m0 = -1e30f, m1 = -1e30f, l0 = 0.f, l1 = 0.f;
    float4 O[8];
    #pragma unroll
    for (int i = 0; i < 8; i++) O[i] = make_float4(0.f, 0.f, 0.f, 0.f);

    for (int kt = 0; kt <= qt; kt++) {
        {
            int row = tid >> 1, seg = (tid & 1) * 32;
            const float* src = g_qkv + (size_t)(b * Tz + kt * 64 + row) * C3z + Cz + h * HDz + seg;
            uint32_t wbuf[32]; unsigned short lsb[32];
            #pragma unroll
            for (int i = 0; i < 8; i++) {
                float4 v = *(const float4*)(src + i * 4);
                float xs[4] = {v.x, v.y, v.z, v.w};
                #pragma unroll
                for (int e = 0; e < 4; e++) {
                    float x = xs[e];
                    __nv_bfloat16 hb = __float2bfloat16(x);
                    unsigned short hu = __bfloat16_as_ushort(hb);
                    __nv_bfloat16 lb = __float2bfloat16(x - __bfloat162float(hb));
                    int i4 = i * 4 + e;
                    wbuf[i4] = (uint32_t)hu | ((uint32_t)hu << 16);
                    lsb[i4] = __bfloat16_as_ushort(lb);
                }
            }
            uint4* d0 = (uint4*)(Ks + row * FA_KST + 2 * seg);
            #pragma unroll
            for (int i = 0; i < 8; i++) d0[i] = ((const uint4*)wbuf)[i];
            uint32_t lw[16];
            #pragma unroll
            for (int j = 0; j < 16; j++)
                lw[j] = (uint32_t)lsb[2 * j] | ((uint32_t)lsb[2 * j + 1] << 16);
            uint4* d1 = (uint4*)(Ks + row * FA_KST + 128 + seg);
            #pragma unroll
            for (int i = 0; i < 4; i++) d1[i] = ((const uint4*)lw)[i];
        }
        {
            int nd = (tid & 15) * 4;
            int k8 = (tid >> 4) * 8;
            unsigned short vh[4][8], vl[4][8];
            #pragma unroll
            for (int kk = 0; kk < 8; kk++) {
                const float* src = g_qkv + (size_t)(b * Tz + kt * 64 + k8 + kk) * C3z + 2 * Cz + h * HDz + nd;
                float4 v = *(const float4*)src;
                float xs[4] = {v.x, v.y, v.z, v.w};
                #pragma unroll
                for (int e = 0; e < 4; e++) {
                    float x = xs[e];
                    __nv_bfloat16 hb = __float2bfloat16(x);
                    __nv_bfloat16 lb = __float2bfloat16(x - __bfloat162float(hb));
                    vh[e][kk] = __bfloat16_as_ushort(hb);
                    vl[e][kk] = __bfloat16_as_ushort(lb);
                }
            }
            #pragma unroll
            for (int e = 0; e < 4; e++) {
                *(uint4*)(Vs + (nd + e) * FA_VST + k8)      = *(const uint4*)vh[e];
                *(uint4*)(Vs + (nd + e) * FA_VST + 64 + k8) = *(const uint4*)vl[e];
            }
        }
        __syncthreads();

        float4 S[8];
        #pragma unroll
        for (int i = 0; i < 8; i++) S[i] = make_float4(0.f, 0.f, 0.f, 0.f);
        #pragma unroll
        for (int ks = 0; ks < 12; ks++) {
            int kb = ks * 16;
            uint32_t ra0, ra1, ra2, ra3;
            ldsm4(ra0, ra1, ra2, ra3, Qb + 2u * (uint32_t)(warp * 16 * FA_QST + aoff + kb));
            #pragma unroll
            for (int pp = 0; pp < 4; pp++) {
                uint32_t b0, b1, b2, b3;
                ldsm4(b0, b1, b2, b3, Kb + 2u * (uint32_t)((pp * 16) * FA_KST + koff + kb));
                mma16816(S[2 * pp],     ra0, ra1, ra2, ra3, b0, b1);
                mma16816(S[2 * pp + 1], ra0, ra1, ra2, ra3, b2, b3);
            }
        }

        if (kt == qt) {
            int r0 = warp * 16 + g, r1 = r0 + 8;
            #pragma unroll
            for (int j = 0; j < 8; j++) {
                int c0 = j * 8 + 2 * tg, c1 = c0 + 1;
                if (c0 > r0) S[j].x = -1e30f;
                if (c1 > r0) S[j].y = -1e30f;
                if (c0 > r1) S[j].z = -1e30f;
                if (c1 > r1) S[j].w = -1e30f;
            }
        }

        float mx0 = -1e30f, mx1 = -1e30f;
        #pragma unroll
        for (int j = 0; j < 8; j++) {
            mx0 = fmaxf(mx0, fmaxf(S[j].x, S[j].y));
            mx1 = fmaxf(mx1, fmaxf(S[j].z, S[j].w));
        }
        mx0 = fmaxf(mx0, __shfl_xor_sync(0xffffffffu, mx0, 1));
        mx0 = fmaxf(mx0, __shfl_xor_sync(0xffffffffu, mx0, 2));
        mx1 = fmaxf(mx1, __shfl_xor_sync(0xffffffffu, mx1, 1));
        mx1 = fmaxf(mx1, __shfl_xor_sync(0xffffffffu, mx1, 2));
        float mn0 = fmaxf(m0, mx0), mn1 = fmaxf(m1, mx1);
        float al0 = __expf(m0 - mn0), al1 = __expf(m1 - mn1);
        m0 = mn0; m1 = mn1;
        float rs0 = 0.f, rs1 = 0.f;
        #pragma unroll
        for (int j = 0; j < 8; j++) {
            S[j].x = __expf(S[j].x - m0);
            S[j].y = __expf(S[j].y - m0);
            S[j].z = __expf(S[j].z - m1);
            S[j].w = __expf(S[j].w - m1);
            rs0 += S[j].x + S[j].y;
            rs1 += S[j].z + S[j].w;
        }
        rs0 += __shfl_xor_sync(0xffffffffu, rs0, 1);
        rs0 += __shfl_xor_sync(0xffffffffu, rs0, 2);
        rs1 += __shfl_xor_sync(0xffffffffu, rs1, 1);
        rs1 += __shfl_xor_sync(0xffffffffu, rs1, 2);
        l0 = l0 * al0 + rs0;
        l1 = l1 * al1 + rs1;
        #pragma unroll
        for (int j = 0; j < 8; j++) {
            O[j].x *= al0; O[j].y *= al0;
            O[j].z *= al1; O[j].w *= al1;
        }

        #pragma unroll
        for (int kc = 0; kc < 4; kc++) {
            float4 s0 = S[2 * kc], s1 = S[2 * kc + 1];
            float f0[8] = {s0.x, s0.y, s0.z, s0.w, s1.x, s1.y, s1.z, s1.w};
            unsigned short phs[8], pls[8];
            #pragma unroll
            for (int e = 0; e < 8; e++) {
                __nv_bfloat16 hb = __float2bfloat16(f0[e]);
                phs[e] = __bfloat16_as_ushort(hb);
                pls[e] = __bfloat16_as_ushort(__float2bfloat16(f0[e] - __bfloat162float(hb)));
            }
            uint32_t ph0 = (uint32_t)phs[0] | ((uint32_t)phs[1] << 16);
            uint32_t ph1 = (uint32_t)phs[2] | ((uint32_t)phs[3] << 16);
            uint32_t ph2 = (uint32_t)phs[4] | ((uint32_t)phs[5] << 16);
            uint32_t ph3 = (uint32_t)phs[6] | ((uint32_t)phs[7] << 16);
            uint32_t pl0 = (uint32_t)pls[0] | ((uint32_t)pls[1] << 16);
            uint32_t pl1 = (uint32_t)pls[2] | ((uint32_t)pls[3] << 16);
            uint32_t pl2 = (uint32_t)pls[4] | ((uint32_t)pls[5] << 16);
            uint32_t pl3 = (uint32_t)pls[6] | ((uint32_t)pls[7] << 16);

            uint32_t vh[8][2], vl[8][2];
            #pragma unroll
            for (int pp = 0; pp < 4; pp++) {
                ldsm4(vh[2*pp][0], vh[2*pp][1], vh[2*pp+1][0], vh[2*pp+1][1],
                      Vb + 2u * (uint32_t)((pp * 16) * FA_VST + voff + kc * 16));
                ldsm4(vl[2*pp][0], vl[2*pp][1], vl[2*pp+1][0], vl[2*pp+1][1],
                      Vb + 2u * (uint32_t)((pp * 16) * FA_VST + voff + 64 + kc * 16));
            }
            #pragma unroll
            for (int nf = 0; nf < 8; nf++) {
                mma16816(O[nf], ph0, ph1, ph2, ph3, vh[nf][0], vh[nf][1]);
                mma16816(O[nf], pl0, pl1, pl2, pl3, vh[nf][0], vh[nf][1]);
                mma16816(O[nf], ph0, ph1, ph2, ph3, vl[nf][0], vl[nf][1]);
            }
        }
        __syncthreads();
    }

    float i0 = 1.0f / l0, i1 = 1.0f / l1;
    int qrow = qt * 64 + warp * 16 + g;
    size_t rb0 = (size_t)(b * Tz + qrow) * (2 * Cz);
    size_t rb1 = (size_t)(b * Tz + qrow + 8) * (2 * Cz);
    #pragma unroll
    for (int nf = 0; nf < 8; nf++) {
        int colg = h * HDz + nf * 8 + 2 * tg;
        float vx = O[nf].x * i0, vy = O[nf].y * i0;
        float wx = O[nf].z * i1, wy = O[nf].w * i1;
        *(uint32_t*)(g_yp + rb0 + colg)      = (uint32_t)bfhi(vx) | ((uint32_t)bfhi(vy) << 16);
        *(uint32_t*)(g_yp + rb0 + Cz + colg) = (uint32_t)bflo(vx) | ((uint32_t)bflo(vy) << 16);
        *(uint32_t*)(g_yp + rb1 + colg)      = (uint32_t)bfhi(wx) | ((uint32_t)bfhi(wy) << 16);
        *(uint32_t*)(g_yp + rb1 + Cz + colg) = (uint32_t)bflo(wx) | ((uint32_t)bflo(wy) << 16);
    }
}

// ---------------- loss ----------------
__global__ void loss_row_kernel(const float* __restrict__ logits,
                                const int* __restrict__ targets) {
    int r = blockIdx.x;
    const float* row = logits + (size_t)r * Vz;
    int tid = threadIdx.x;
    float mx = -1e30f;
    for (int j = tid; j < Vz; j += 256) mx = fmaxf(mx, row[j]);
    mx = blockReduceMax(mx);
    float s = 0.f;
    for (int j = tid; j < Vz; j += 256) s += expf(row[j] - mx);
    s = blockReduceSum(s);
    if (tid == 0) {
        int t = targets[r];
        g_red[r] = -(row[t] - mx - logf(s));
    }
}

__global__ void loss_final_kernel(float* __restrict__ out, int out_size) {
    int tid = threadIdx.x;
    float s = 0.f;
    for (int j = tid; j < BTz; j += 256) s += g_red[j];
    s = blockReduceSum(s);
    if (tid == 0) {
        long long logits_elems = (long long)BTz * Vz;
        if ((long long)out_size > logits_elems)
            out[logits_elems] = s / (float)BTz;
    }
}

// ---------------- launch ----------------
extern "C" void kernel_launch(void* const* d_in, const int* in_sizes, int n_in,
                              void* d_out, int out_size) {
    const int*   idx     = (const int*)d_in[0];
    const int*   targets = (const int*)d_in[1];
    const float* tok_emb = (const float*)d_in[2];
    const float* pos_emb = (const float*)d_in[3];
    const float* ln1_w   = (const float*)d_in[4];
    const float* ln1_b   = (const float*)d_in[5];
    const float* ln2_w   = (const float*)d_in[6];
    const float* ln2_b   = (const float*)d_in[7];
    const float* Wq = (const float*)d_in[8];
    const float* bq = (const float*)d_in[9];
    const float* Wk = (const float*)d_in[10];
    const float* bk = (const float*)d_in[11];
    const float* Wv = (const float*)d_in[12];
    const float* bv = (const float*)d_in[13];
    const float* Wo = (const float*)d_in[14];
    const float* bo = (const float*)d_in[15];
    const float* W1 = (const float*)d_in[16];
    const float* b1 = (const float*)d_in[17];
    const float* W2 = (const float*)d_in[18];
    const float* b2 = (const float*)d_in[19];
    const float* lnf_w  = (const float*)d_in[20];
    const float* lnf_b  = (const float*)d_in[21];
    const float* head_w = (const float*)d_in[22];
    float* out = (float*)d_out;

    float *px, *pbp, *pwp, *pqkv;
    __nv_bfloat16 *php, *pffp, *pyp;
    cudaGetSymbolAddress((void**)&px,   g_x);
    cudaGetSymbolAddress((void**)&pbp,  g_bpack);
    cudaGetSymbolAddress((void**)&pwp,  g_wpack);
    cudaGetSymbolAddress((void**)&pqkv, g_qkv);
    cudaGetSymbolAddress((void**)&php,  g_hp);
    cudaGetSymbolAddress((void**)&pffp, g_ffp);
    cudaGetSymbolAddress((void**)&pyp,  g_yp);

    cudaFuncSetAttribute(gemm_pk_kernel<0, false>, cudaFuncAttributeMaxDynamicSharedMemorySize, GSMEM);
    cudaFuncSetAttribute(gemm_pk_kernel<1, false>, cudaFuncAttributeMaxDynamicSharedMemorySize, GSMEM);
    cudaFuncSetAttribute(gemm_pk_kernel<2, false>, cudaFuncAttributeMaxDynamicSharedMemorySize, GSMEM);
    cudaFuncSetAttribute(gemm_pk_kernel<3, true >, cudaFuncAttributeMaxDynamicSharedMemorySize, GSMEM);
    cudaFuncSetAttribute(attn_fused_kernel, cudaFuncAttributeMaxDynamicSharedMemorySize, FA_SMEM);

    embed_kernel<<<BTz, 256>>>(idx, tok_emb, pos_emb);

    const size_t CC  = (size_t)Cz * Cz;
    const size_t C14 = (size_t)Cz * C4z;
    dim3 gQKV(C3z / 64, 16), gCC(Cz / 64, 16), gC4(C4z / 64, 16);
    dim3 gHead((Vz + 63) / 64, 16);

    for (int l = 0; l < Lz; l++) {
        pack_w_kernel<<<dim3(Cz, 3), 256>>>(Wq + l * CC, Wk + l * CC, Wv + l * CC);
        pack_bias_kernel<<<3, 256>>>(bq + (size_t)l * Cz, bk + (size_t)l * Cz, bv + (size_t)l * Cz);
        ln_pack_kernel<<<BTz, 256>>>(px, ln1_w + (size_t)l * Cz, ln1_b + (size_t)l * Cz, php);
        gemm_pk_kernel<0, false><<<gQKV, 256, GSMEM>>>(php, pwp, pbp, nullptr, pqkv, nullptr, C3z, Cz);
        attn_fused_kernel<<<dim3(Tz / 64, Bz * Hz), 128, FA_SMEM>>>();
        gemm_pk_kernel<1, false><<<gCC, 256, GSMEM>>>(pyp, Wo + l * CC, bo + (size_t)l * Cz, px, px, nullptr, Cz, Cz);
        ln_pack_kernel<<<BTz, 256>>>(px, ln2_w + (size_t)l * Cz, ln2_b + (size_t)l * Cz, php);
        gemm_pk_kernel<2, false><<<gC4, 256, GSMEM>>>(php, W1 + l * C14, b1 + (size_t)l * C4z, nullptr, nullptr, pffp, C4z, Cz);
        gemm_pk_kernel<1, false><<<gCC, 256, GSMEM>>>(pffp, W2 + l * C14, b2 + (size_t)l * Cz, px, px, nullptr, Cz, C4z);
    }

    ln_pack_kernel<<<BTz, 256>>>(px, lnf_w, lnf_b, php);
    gemm_pk_kernel<3, true><<<gHead, 256, GSMEM>>>(php, head_w, nullptr, nullptr, out, nullptr, Vz, Cz);
    loss_row_kernel<<<BTz, 256>>>(out, targets);
    loss_final_kernel<<<1, 256>>>(out, out_size);
}

// round 15
// speedup vs baseline: 1.1690x; 1.0938x over previous
#include <cuda_runtime.h>
#include <cuda_bf16.h>
#include <math.h>
#include <stdint.h>

#define Bz 2
#define Tz 1024
#define Cz 1024
#define Hz 16
#define HDz 64
#define Lz 12
#define Vz 50257
#define BTz (Bz*Tz)
#define C4z (4*Cz)
#define C3z (3*Cz)

// ---------------- scratch (device globals; no allocation) ----------------
__device__ float g_x[BTz*Cz];                         // residual (fp32)
__device__ float g_qkv[(size_t)BTz*C3z];              // QKV output (fp32, attn input)
__device__ float g_red[BTz];
__device__ __nv_bfloat16 g_hp [(size_t)BTz*2*Cz];     // LN output [hi K | lo K]
__device__ __nv_bfloat16 g_yp [(size_t)BTz*2*Cz];     // attn output [hi | lo]
__device__ __nv_bfloat16 g_ffp[(size_t)BTz*2*C4z];    // MLP hidden [hi | lo]

// ---------------- helpers ----------------
__device__ __forceinline__ unsigned short bfhi(float x) {
    return __bfloat16_as_ushort(__float2bfloat16(x));
}
__device__ __forceinline__ unsigned short bflo(float x) {
    __nv_bfloat16 h = __float2bfloat16(x);
    return __bfloat16_as_ushort(__float2bfloat16(x - __bfloat162float(h)));
}

__device__ __forceinline__ float blockReduceSum(float v) {
    __shared__ float sh[33];
    int lane = threadIdx.x & 31, w = threadIdx.x >> 5;
    #pragma unroll
    for (int o = 16; o; o >>= 1) v += __shfl_down_sync(0xffffffffu, v, o);
    __syncthreads();
    if (lane == 0) sh[w] = v;
    __syncthreads();
    if (threadIdx.x == 0) {
        float s = 0.f;
        int nw = blockDim.x >> 5;
        for (int i = 0; i < nw; i++) s += sh[i];
        sh[32] = s;
    }
    __syncthreads();
    return sh[32];
}

__device__ __forceinline__ float blockReduceMax(float v) {
    __shared__ float sh[33];
    int lane = threadIdx.x & 31, w = threadIdx.x >> 5;
    #pragma unroll
    for (int o = 16; o; o >>= 1) v = fmaxf(v, __shfl_down_sync(0xffffffffu, v, o));
    __syncthreads();
    if (lane == 0) sh[w] = v;
    __syncthreads();
    if (threadIdx.x == 0) {
        float s = -1e30f;
        int nw = blockDim.x >> 5;
        for (int i = 0; i < nw; i++) s = fmaxf(s, sh[i]);
        sh[32] = s;
    }
    __syncthreads();
    return sh[32];
}

// ---------------- embedding ----------------
__global__ void embed_kernel(const int* __restrict__ idx,
                             const float* __restrict__ tok,
                             const float* __restrict__ pos) {
    int r = blockIdx.x;
    int c = threadIdx.x * 4;
    int tokid = idx[r];
    float4 te = *(const float4*)(tok + (size_t)tokid * Cz + c);
    float4 pe = *(const float4*)(pos + (size_t)(r % Tz) * Cz + c);
    float4 o;
    o.x = te.x + pe.x; o.y = te.y + pe.y; o.z = te.z + pe.z; o.w = te.w + pe.w;
    *(float4*)(g_x + (size_t)r * Cz + c) = o;
}

// ---------------- layernorm -> packed A rows [hi C | lo C] ----------------
__global__ void ln_pack_kernel(const float* __restrict__ x,
                               const float* __restrict__ w,
                               const float* __restrict__ b,
                               __nv_bfloat16* __restrict__ outp) {
    int r = blockIdx.x;
    const float* xr = x + (size_t)r * Cz;
    float v[4];
    #pragma unroll
    for (int k = 0; k < 4; k++) v[k] = xr[threadIdx.x + k * 256];
    float s = v[0] + v[1] + v[2] + v[3];
    s = blockReduceSum(s);
    float mu = s * (1.0f / Cz);
    float sq = 0.f;
    #pragma unroll
    for (int k = 0; k < 4; k++) { float d = v[k] - mu; sq += d * d; }
    sq = blockReduceSum(sq);
    float rstd = rsqrtf(sq * (1.0f / Cz) + 1e-5f);
    __nv_bfloat16* orow = outp + (size_t)r * 2 * Cz;
    #pragma unroll
    for (int k = 0; k < 4; k++) {
        int c = threadIdx.x + k * 256;
        float xv = (v[k] - mu) * rstd * w[c] + b[c];
        __nv_bfloat16 hb = __float2bfloat16(xv);
        orow[c] = hb;
        orow[Cz + c] = __float2bfloat16(xv - __bfloat162float(hb));
    }
}

// ---------------- mma / ldmatrix primitives ----------------
__device__ __forceinline__ void mma16816(float4& c, uint32_t a0, uint32_t a1,
                                         uint32_t a2, uint32_t a3,
                                         uint32_t b0, uint32_t b1) {
    asm volatile(
        "mma.sync.aligned.m16n8k16.row.col.f32.bf16.bf16.f32 "
        "{%0,%1,%2,%3}, {%4,%5,%6,%7}, {%8,%9}, {%0,%1,%2,%3};"
        : "+f"(c.x), "+f"(c.y), "+f"(c.z), "+f"(c.w)
        : "r"(a0), "r"(a1), "r"(a2), "r"(a3), "r"(b0), "r"(b1));
}

__device__ __forceinline__ void ldsm4(uint32_t& r0, uint32_t& r1,
                                      uint32_t& r2, uint32_t& r3, uint32_t addr) {
    asm volatile("ldmatrix.sync.aligned.m8n8.x4.shared.b16 {%0,%1,%2,%3}, [%4];"
        : "=r"(r0), "=r"(r1), "=r"(r2), "=r"(r3) : "r"(addr));
}

// =========================================================================
// GEMM 128x128 tile (1 CTA/SM), shared-segment hi/lo, 3 MMA passes/kstep.
// RACE-FREE pipeline: PREFA issued AFTER the barrier.
// QKV3: B/bias selected per-block from 3 matrices (tile-aligned at 1024).
// EPI: 0=bias->f32, 1=bias+res->f32, 2=bias+gelu->packed[hi|lo], 3=plain->f32
// =========================================================================
#define AST 72
#define ATILEB (128*AST*2)        // 18432 B per side
#define BUFSZ (2*ATILEB)          // 36864 B per stage
#define GSMEM (2*BUFSZ)           // 73728 B

#define CPA(dst, src) asm volatile("cp.async.cg.shared.global [%0], [%1], 16;\n" :: "r"(dst), "l"(src))

template<int EPI, bool NGUARD, bool QKV3>
__global__ void __launch_bounds__(256, 1)
gemm_pk_kernel(const __nv_bfloat16* __restrict__ Apack,
               const float* __restrict__ Bm0, const float* __restrict__ Bm1,
               const float* __restrict__ Bm2,
               const float* __restrict__ bias0, const float* __restrict__ bias1,
               const float* __restrict__ bias2,
               const float* __restrict__ res,
               float* __restrict__ outF, __nv_bfloat16* __restrict__ outP,
               int N, int K) {
    extern __shared__ __nv_bfloat16 smem[];
    int tid = threadIdx.x, lane = tid & 31, warp = tid >> 5;
    int wm = warp & 1, wn = warp >> 1;
    int g = lane >> 2, tg = lane & 3;
    int rowBlk = blockIdx.y * 128, colBlk = blockIdx.x * 128;
    int row2 = tid >> 1, h2 = tid & 1;          // A staging: 128 rows x {hi,lo}
    int bn = tid & 127, kseg = tid >> 7;        // B staging: 128 cols x 2 k-halves
    int t8 = lane >> 3, r8 = lane & 7;
    int aoff = ((t8 & 1) * 8 + r8) * AST + (t8 >> 1) * 8;
    int boff = ((t8 >> 1) * 8 + r8) * AST + (t8 & 1) * 8;
    uint32_t sbase = (uint32_t)__cvta_generic_to_shared(smem);

    // B matrix / bias selection (QKV3: 1024-column matrices, 128-wide tiles align)
    const float* BmS = Bm0;
    const float* biasS = bias0;
    int colLoc = colBlk;
    if (QKV3) {
        int mat = colBlk >> 10;
        BmS   = (mat == 0) ? Bm0   : (mat == 1) ? Bm1   : Bm2;
        biasS = (mat == 0) ? bias0 : (mat == 1) ? bias1 : bias2;
        colLoc = colBlk & 1023;
    }
    const int NB = QKV3 ? Cz : N;   // B row stride

    const __nv_bfloat16* aRow = Apack + (size_t)(rowBlk + row2) * (2 * K) + (size_t)h2 * K;
    int nb = colLoc + bn;
    bool bValid = (!NGUARD) || (nb < N);
    const float* bPtr = BmS + (bValid ? nb : 0);

    float fb[16];
    float4 acc[4][4];
    #pragma unroll
    for (int i = 0; i < 4; i++)
        #pragma unroll
        for (int j = 0; j < 4; j++) acc[i][j] = make_float4(0.f, 0.f, 0.f, 0.f);

#define PREFA(s, kt) { \
        uint32_t ad_ = sbase + (s) * BUFSZ + (uint32_t)(row2 * AST + h2 * 32) * 2; \
        const __nv_bfloat16* sA_ = aRow + (kt) * 32; \
        CPA(ad_, sA_); CPA(ad_ + 16, sA_ + 8); CPA(ad_ + 32, sA_ + 16); CPA(ad_ + 48, sA_ + 24); \
        asm volatile("cp.async.commit_group;\n"); }

#define LDGB(kt) { const float* p = bPtr + (size_t)((kt) * 32 + kseg * 16) * NB; \
        _Pragma("unroll") \
        for (int i = 0; i < 16; i++) fb[i] = (!NGUARD || bValid) ? p[(size_t)i * NB] : 0.f; }

#define CVTB(s) { \
        unsigned short hs_[16], ls_[16]; \
        _Pragma("unroll") \
        for (int i = 0; i < 16; i++) { \
            float x = fb[i]; \
            __nv_bfloat16 h = __float2bfloat16(x); \
            hs_[i] = __bfloat16_as_ushort(h); \
            ls_[i] = __bfloat16_as_ushort(__float2bfloat16(x - __bfloat162float(h))); } \
        __nv_bfloat16* Bs_ = smem + ((s) * BUFSZ + ATILEB) / 2 + bn * AST; \
        uint4* dh = (uint4*)(Bs_ + kseg * 16); \
        dh[0] = ((const uint4*)hs_)[0]; dh[1] = ((const uint4*)hs_)[1]; \
        uint4* dl = (uint4*)(Bs_ + 32 + kseg * 16); \
        dl[0] = ((const uint4*)ls_)[0]; dl[1] = ((const uint4*)ls_)[1]; }

#define MMAS(s) { uint32_t Ab = sbase + (s) * BUFSZ; \
        uint32_t Bb = Ab + ATILEB; \
        _Pragma("unroll") \
        for (int kh = 0; kh < 2; kh++) { \
            int kbh = kh * 16; \
            uint32_t ah[4][4], al[4][4], rbh[4][2], rbl[4][2]; \
            _Pragma("unroll") \
            for (int mf = 0; mf < 4; mf++) { \
                ldsm4(ah[mf][0], ah[mf][1], ah[mf][2], ah[mf][3], \
                      Ab + 2u * (uint32_t)((wm * 64 + mf * 16) * AST + aoff + kbh)); \
                ldsm4(al[mf][0], al[mf][1], al[mf][2], al[mf][3], \
                      Ab + 2u * (uint32_t)((wm * 64 + mf * 16) * AST + aoff + 32 + kbh)); } \
            _Pragma("unroll") \
            for (int p = 0; p < 2; p++) { \
                ldsm4(rbh[2*p][0], rbh[2*p][1], rbh[2*p+1][0], rbh[2*p+1][1], \
                      Bb + 2u * (uint32_t)((wn * 32 + p * 16) * AST + boff + kbh)); \
                ldsm4(rbl[2*p][0], rbl[2*p][1], rbl[2*p+1][0], rbl[2*p+1][1], \
                      Bb + 2u * (uint32_t)((wn * 32 + p * 16) * AST + boff + 32 + kbh)); } \
            _Pragma("unroll") \
            for (int mf = 0; mf < 4; mf++) \
                _Pragma("unroll") \
                for (int nf = 0; nf < 4; nf++) { \
                    mma16816(acc[mf][nf], ah[mf][0], ah[mf][1], ah[mf][2], ah[mf][3], \
                             rbh[nf][0], rbh[nf][1]); \
                    mma16816(acc[mf][nf], al[mf][0], al[mf][1], al[mf][2], al[mf][3], \
                             rbh[nf][0], rbh[nf][1]); \
                    mma16816(acc[mf][nf], ah[mf][0], ah[mf][1], ah[mf][2], ah[mf][3], \
                             rbl[nf][0], rbl[nf][1]); } } }

    int nt = K / 32;
    PREFA(0, 0);
    LDGB(0);
    CVTB(0);
    for (int kt = 0; kt < nt; kt++) {
        int s = kt & 1;
        if (kt + 1 < nt) LDGB(kt + 1);
        asm volatile("cp.async.wait_group 0;\n" ::: "memory");
        __syncthreads();
        // PREFA after the barrier: buffer s^1's readers (MMAS@kt-1) are done.
        if (kt + 1 < nt) PREFA(s ^ 1, kt + 1);
        MMAS(s);
        if (kt + 1 < nt) CVTB(s ^ 1);
    }

    // ---- epilogue ----
    #pragma unroll
    for (int mf = 0; mf < 4; mf++) {
        int row0 = rowBlk + wm * 64 + mf * 16 + g;
        #pragma unroll
        for (int nf = 0; nf < 4; nf++) {
            int colOff = wn * 32 + nf * 8 + tg * 2;
            int col = colBlk + colOff;
            int colB = colLoc + colOff;
            float vals[4] = {acc[mf][nf].x, acc[mf][nf].y, acc[mf][nf].z, acc[mf][nf].w};
            #pragma unroll
            for (int h = 0; h < 2; h++) {
                int row = row0 + h * 8;
                float v0 = vals[h * 2], v1 = vals[h * 2 + 1];
                if (EPI == 0 || EPI == 1 || EPI == 2) {
                    v0 += biasS[colB]; v1 += biasS[colB + 1];
                }
                if (EPI == 2) {
                    v0 = 0.5f * v0 * (1.0f + erff(v0 * 0.7071067811865476f));
                    v1 = 0.5f * v1 * (1.0f + erff(v1 * 0.7071067811865476f));
                }
                if (EPI == 1) {
                    v0 += res[(size_t)row * N + col];
                    v1 += res[(size_t)row * N + col + 1];
                }
                if (EPI == 2) {
                    size_t rowb = (size_t)row * (size_t)(2 * N);
                    *(uint32_t*)(outP + rowb + col) =
                        (uint32_t)bfhi(v0) | ((uint32_t)bfhi(v1) << 16);
                    *(uint32_t*)(outP + rowb + N + col) =
                        (uint32_t)bflo(v0) | ((uint32_t)bflo(v1) << 16);
                } else {
                    if (!NGUARD || col < N)     outF[(size_t)row * N + col] = v0;
                    if (!NGUARD || col + 1 < N) outF[(size_t)row * N + col + 1] = v1;
                }
            }
        }
    }
#undef PREFA
#undef LDGB
#undef CVTB
#undef MMAS
}

// =========================================================================
// Fused flash attention (epilogue writes g_yp [hi C | lo C])
// =========================================================================
#define FA_QST 200
#define FA_KST 200
#define FA_VST 136
#define FA_SMEM ((64*FA_QST + 64*FA_KST + 64*FA_VST)*2)

__global__ void __launch_bounds__(128, 2)
attn_fused_kernel() {
    extern __shared__ __nv_bfloat16 sm[];
    __nv_bfloat16* Qs = sm;
    __nv_bfloat16* Ks = sm + 64 * FA_QST;
    __nv_bfloat16* Vs = sm + 64 * (FA_QST + FA_KST);
    int tid = threadIdx.x, lane = tid & 31, warp = tid >> 5;
    int qt = blockIdx.x, bh = blockIdx.y;
    int b = bh >> 4, h = bh & 15;
    int g = lane >> 2, tg = lane & 3;
    int t8 = lane >> 3, r8 = lane & 7;
    uint32_t sbb = (uint32_t)__cvta_generic_to_shared(sm);
    uint32_t Qb = sbb;
    uint32_t Kb = sbb + 64 * FA_QST * 2;
    uint32_t Vb = sbb + 64 * (FA_QST + FA_KST) * 2;
    int aoff = ((t8 & 1) * 8 + r8) * FA_QST + (t8 >> 1) * 8;
    int koff = ((t8 >> 1) * 8 + r8) * FA_KST + (t8 & 1) * 8;
    int voff = ((t8 >> 1) * 8 + r8) * FA_VST + (t8 & 1) * 8;

    {
        int row = tid >> 1, seg = (tid & 1) * 32;
        const float* src = g_qkv + (size_t)(b * Tz + qt * 64 + row) * C3z + h * HDz + seg;
        uint32_t wbuf[32]; unsigned short hsb[32];
        #pragma unroll
        for (int i = 0; i < 8; i++) {
            float4 v = *(const float4*)(src + i * 4);
            float xs[4] = {v.x, v.y, v.z, v.w};
            #pragma unroll
            for (int e = 0; e < 4; e++) {
                float x = xs[e] * 0.125f;
                __nv_bfloat16 hb = __float2bfloat16(x);
                __nv_bfloat16 lb = __float2bfloat16(x - __bfloat162float(hb));
                int i4 = i * 4 + e;
                wbuf[i4] = (uint32_t)__bfloat16_as_ushort(hb) |
                           ((uint32_t)__bfloat16_as_ushort(lb) << 16);
                hsb[i4] = __bfloat16_as_ushort(hb);
            }
        }
        uint4* d0 = (uint4*)(Qs + row * FA_QST + 2 * seg);
        #pragma unroll
        for (int i = 0; i < 8; i++) d0[i] = ((const uint4*)wbuf)[i];
        uint32_t hw[16];
        #pragma unroll
        for (int j = 0; j < 16; j++)
            hw[j] = (uint32_t)hsb[2 * j] | ((uint32_t)hsb[2 * j + 1] << 16);
        uint4* d1 = (uint4*)(Qs + row * FA_QST + 128 + seg);
        #pragma unroll
        for (int i = 0; i < 4; i++) d1[i] = ((const uint4*)hw)[i];
    }

    float m0 = -1e30f, m1 = -1e30f, l0 = 0.f, l1 = 0.f;
    float4 O[8];
    #pragma unroll
    for (int i = 0; i < 8; i++) O[i] = make_float4(0.f, 0.f, 0.f, 0.f);

    for (int kt = 0; kt <= qt; kt++) {
        {
            int row = tid >> 1, seg = (tid & 1) * 32;
            const float* src = g_qkv + (size_t)(b * Tz + kt * 64 + row) * C3z + Cz + h * HDz + seg;
            uint32_t wbuf[32]; unsigned short lsb[32];
            #pragma unroll
            for (int i = 0; i < 8; i++) {
                float4 v = *(const float4*)(src + i * 4);
                float xs[4] = {v.x, v.y, v.z, v.w};
                #pragma unroll
                for (int e = 0; e < 4; e++) {
                    float x = xs[e];
                    __nv_bfloat16 hb = __float2bfloat16(x);
                    unsigned short hu = __bfloat16_as_ushort(hb);
                    __nv_bfloat16 lb = __float2bfloat16(x - __bfloat162float(hb));
                    int i4 = i * 4 + e;
                    wbuf[i4] = (uint32_t)hu | ((uint32_t)hu << 16);
                    lsb[i4] = __bfloat16_as_ushort(lb);
                }
            }
            uint4* d0 = (uint4*)(Ks + row * FA_KST + 2 * seg);
            #pragma unroll
            for (int i = 0; i < 8; i++) d0[i] = ((const uint4*)wbuf)[i];
            uint32_t lw[16];
            #pragma unroll
            for (int j = 0; j < 16; j++)
                lw[j] = (uint32_t)lsb[2 * j] | ((uint32_t)lsb[2 * j + 1] << 16);
            uint4* d1 = (uint4*)(Ks + row * FA_KST + 128 + seg);
            #pragma unroll
            for (int i = 0; i < 4; i++) d1[i] = ((const uint4*)lw)[i];
        }
        {
            int nd = (tid & 15) * 4;
            int k8 = (tid >> 4) * 8;
            unsigned short vh[4][8], vl[4][8];
            #pragma unroll
            for (int kk = 0; kk < 8; kk++) {
                const float* src = g_qkv + (size_t)(b * Tz + kt * 64 + k8 + kk) * C3z + 2 * Cz + h * HDz + nd;
                float4 v = *(const float4*)src;
                float xs[4] = {v.x, v.y, v.z, v.w};
                #pragma unroll
                for (int e = 0; e < 4; e++) {
                    float x = xs[e];
                    __nv_bfloat16 hb = __float2bfloat16(x);
                    __nv_bfloat16 lb = __float2bfloat16(x - __bfloat162float(hb));
                    vh[e][kk] = __bfloat16_as_ushort(hb);
                    vl[e][kk] = __bfloat16_as_ushort(lb);
                }
            }
            #pragma unroll
            for (int e = 0; e < 4; e++) {
                *(uint4*)(Vs + (nd + e) * FA_VST + k8)      = *(const uint4*)vh[e];
                *(uint4*)(Vs + (nd + e) * FA_VST + 64 + k8) = *(const uint4*)vl[e];
            }
        }
        __syncthreads();

        float4 S[8];
        #pragma unroll
        for (int i = 0; i < 8; i++) S[i] = make_float4(0.f, 0.f, 0.f, 0.f);
        #pragma unroll
        for (int ks = 0; ks < 12; ks++) {
            int kb = ks * 16;
            uint32_t ra0, ra1, ra2, ra3;
            ldsm4(ra0, ra1, ra2, ra3, Qb + 2u * (uint32_t)(warp * 16 * FA_QST + aoff + kb));
            #pragma unroll
            for (int pp = 0; pp < 4; pp++) {
                uint32_t b0, b1, b2, b3;
                ldsm4(b0, b1, b2, b3, Kb + 2u * (uint32_t)((pp * 16) * FA_KST + koff + kb));
                mma16816(S[2 * pp],     ra0, ra1, ra2, ra3, b0, b1);
                mma16816(S[2 * pp + 1], ra0, ra1, ra2, ra3, b2, b3);
            }
        }

        if (kt == qt) {
            int r0 = warp * 16 + g, r1 = r0 + 8;
            #pragma unroll
            for (int j = 0; j < 8; j++) {
                int c0 = j * 8 + 2 * tg, c1 = c0 + 1;
                if (c0 > r0) S[j].x = -1e30f;
                if (c1 > r0) S[j].y = -1e30f;
                if (c0 > r1) S[j].z = -1e30f;
                if (c1 > r1) S[j].w = -1e30f;
            }
        }

        float mx0 = -1e30f, mx1 = -1e30f;
        #pragma unroll
        for (int j = 0; j < 8; j++) {
            mx0 = fmaxf(mx0, fmaxf(S[j].x, S[j].y));
            mx1 = fmaxf(mx1, fmaxf(S[j].z, S[j].w));
        }
        mx0 = fmaxf(mx0, __shfl_xor_sync(0xffffffffu, mx0, 1));
        mx0 = fmaxf(mx0, __shfl_xor_sync(0xffffffffu, mx0, 2));
        mx1 = fmaxf(mx1, __shfl_xor_sync(0xffffffffu, mx1, 1));
        mx1 = fmaxf(mx1, __shfl_xor_sync(0xffffffffu, mx1, 2));
        float mn0 = fmaxf(m0, mx0), mn1 = fmaxf(m1, mx1);
        float al0 = __expf(m0 - mn0), al1 = __expf(m1 - mn1);
        m0 = mn0; m1 = mn1;
        float rs0 = 0.f, rs1 = 0.f;
        #pragma unroll
        for (int j = 0; j < 8; j++) {
            S[j].x = __expf(S[j].x - m0);
            S[j].y = __expf(S[j].y - m0);
            S[j].z = __expf(S[j].z - m1);
            S[j].w = __expf(S[j].w - m1);
            rs0 += S[j].x + S[j].y;
            rs1 += S[j].z + S[j].w;
        }
        rs0 += __shfl_xor_sync(0xffffffffu, rs0, 1);
        rs0 += __shfl_xor_sync(0xffffffffu, rs0, 2);
        rs1 += __shfl_xor_sync(0xffffffffu, rs1, 1);
        rs1 += __shfl_xor_sync(0xffffffffu, rs1, 2);
        l0 = l0 * al0 + rs0;
        l1 = l1 * al1 + rs1;
        #pragma unroll
        for (int j = 0; j < 8; j++) {
            O[j].x *= al0; O[j].y *= al0;
            O[j].z *= al1; O[j].w *= al1;
        }

        #pragma unroll
        for (int kc = 0; kc < 4; kc++) {
            float4 s0 = S[2 * kc], s1 = S[2 * kc + 1];
            float f0[8] = {s0.x, s0.y, s0.z, s0.w, s1.x, s1.y, s1.z, s1.w};
            unsigned short phs[8], pls[8];
            #pragma unroll
            for (int e = 0; e < 8; e++) {
                __nv_bfloat16 hb = __float2bfloat16(f0[e]);
                phs[e] = __bfloat16_as_ushort(hb);
                pls[e] = __bfloat16_as_ushort(__float2bfloat16(f0[e] - __bfloat162float(hb)));
            }
            uint32_t ph0 = (uint32_t)phs[0] | ((uint32_t)phs[1] << 16);
            uint32_t ph1 = (uint32_t)phs[2] | ((uint32_t)phs[3] << 16);
            uint32_t ph2 = (uint32_t)phs[4] | ((uint32_t)phs[5] << 16);
            uint32_t ph3 = (uint32_t)phs[6] | ((uint32_t)phs[7] << 16);
            uint32_t pl0 = (uint32_t)pls[0] | ((uint32_t)pls[1] << 16);
            uint32_t pl1 = (uint32_t)pls[2] | ((uint32_t)pls[3] << 16);
            uint32_t pl2 = (uint32_t)pls[4] | ((uint32_t)pls[5] << 16);
            uint32_t pl3 = (uint32_t)pls[6] | ((uint32_t)pls[7] << 16);

            uint32_t vh[8][2], vl[8][2];
            #pragma unroll
            for (int pp = 0; pp < 4; pp++) {
                ldsm4(vh[2*pp][0], vh[2*pp][1], vh[2*pp+1][0], vh[2*pp+1][1],
                      Vb + 2u * (uint32_t)((pp * 16) * FA_VST + voff + kc * 16));
                ldsm4(vl[2*pp][0], vl[2*pp][1], vl[2*pp+1][0], vl[2*pp+1][1],
                      Vb + 2u * (uint32_t)((pp * 16) * FA_VST + voff + 64 + kc * 16));
            }
            #pragma unroll
            for (int nf = 0; nf < 8; nf++) {
                mma16816(O[nf], ph0, ph1, ph2, ph3, vh[nf][0], vh[nf][1]);
                mma16816(O[nf], pl0, pl1, pl2, pl3, vh[nf][0], vh[nf][1]);
                mma16816(O[nf], ph0, ph1, ph2, ph3, vl[nf][0], vl[nf][1]);
            }
        }
        __syncthreads();
    }

    float i0 = 1.0f / l0, i1 = 1.0f / l1;
    int qrow = qt * 64 + warp * 16 + g;
    size_t rb0 = (size_t)(b * Tz + qrow) * (2 * Cz);
    size_t rb1 = (size_t)(b * Tz + qrow + 8) * (2 * Cz);
    #pragma unroll
    for (int nf = 0; nf < 8; nf++) {
        int colg = h * HDz + nf * 8 + 2 * tg;
        float vx = O[nf].x * i0, vy = O[nf].y * i0;
        float wx = O[nf].z * i1, wy = O[nf].w * i1;
        *(uint32_t*)(g_yp + rb0 + colg)      = (uint32_t)bfhi(vx) | ((uint32_t)bfhi(vy) << 16);
        *(uint32_t*)(g_yp + rb0 + Cz + colg) = (uint32_t)bflo(vx) | ((uint32_t)bflo(vy) << 16);
        *(uint32_t*)(g_yp + rb1 + colg)      = (uint32_t)bfhi(wx) | ((uint32_t)bfhi(wy) << 16);
        *(uint32_t*)(g_yp + rb1 + Cz + colg) = (uint32_t)bflo(wx) | ((uint32_t)bflo(wy) << 16);
    }
}

// ---------------- loss ----------------
__global__ void loss_row_kernel(const float* __restrict__ logits,
                                const int* __restrict__ targets) {
    int r = blockIdx.x;
    const float* row = logits + (size_t)r * Vz;
    int tid = threadIdx.x;
    float mx = -1e30f;
    for (int j = tid; j < Vz; j += 256) mx = fmaxf(mx, row[j]);
    mx = blockReduceMax(mx);
    float s = 0.f;
    for (int j = tid; j < Vz; j += 256) s += expf(row[j] - mx);
    s = blockReduceSum(s);
    if (tid == 0) {
        int t = targets[r];
        g_red[r] = -(row[t] - mx - logf(s));
    }
}

__global__ void loss_final_kernel(float* __restrict__ out, int out_size) {
    int tid = threadIdx.x;
    float s = 0.f;
    for (int j = tid; j < BTz; j += 256) s += g_red[j];
    s = blockReduceSum(s);
    if (tid == 0) {
        long long logits_elems = (long long)BTz * Vz;
        if ((long long)out_size > logits_elems)
            out[logits_elems] = s / (float)BTz;
    }
}

// ---------------- launch ----------------
extern "C" void kernel_launch(void* const* d_in, const int* in_sizes, int n_in,
                              void* d_out, int out_size) {
    const int*   idx     = (const int*)d_in[0];
    const int*   targets = (const int*)d_in[1];
    const float* tok_emb = (const float*)d_in[2];
    const float* pos_emb = (const float*)d_in[3];
    const float* ln1_w   = (const float*)d_in[4];
    const float* ln1_b   = (const float*)d_in[5];
    const float* ln2_w   = (const float*)d_in[6];
    const float* ln2_b   = (const float*)d_in[7];
    const float* Wq = (const float*)d_in[8];
    const float* bq = (const float*)d_in[9];
    const float* Wk = (const float*)d_in[10];
    const float* bk = (const float*)d_in[11];
    const float* Wv = (const float*)d_in[12];
    const float* bv = (const float*)d_in[13];
    const float* Wo = (const float*)d_in[14];
    const float* bo = (const float*)d_in[15];
    const float* W1 = (const float*)d_in[16];
    const float* b1 = (const float*)d_in[17];
    const float* W2 = (const float*)d_in[18];
    const float* b2 = (const float*)d_in[19];
    const float* lnf_w  = (const float*)d_in[20];
    const float* lnf_b  = (const float*)d_in[21];
    const float* head_w = (const float*)d_in[22];
    float* out = (float*)d_out;

    float *px, *pqkv;
    __nv_bfloat16 *php, *pffp, *pyp;
    cudaGetSymbolAddress((void**)&px,   g_x);
    cudaGetSymbolAddress((void**)&pqkv, g_qkv);
    cudaGetSymbolAddress((void**)&php,  g_hp);
    cudaGetSymbolAddress((void**)&pffp, g_ffp);
    cudaGetSymbolAddress((void**)&pyp,  g_yp);

    cudaFuncSetAttribute(gemm_pk_kernel<0, false, true >, cudaFuncAttributeMaxDynamicSharedMemorySize, GSMEM);
    cudaFuncSetAttribute(gemm_pk_kernel<1, false, false>, cudaFuncAttributeMaxDynamicSharedMemorySize, GSMEM);
    cudaFuncSetAttribute(gemm_pk_kernel<2, false, false>, cudaFuncAttributeMaxDynamicSharedMemorySize, GSMEM);
    cudaFuncSetAttribute(gemm_pk_kernel<3, true , false>, cudaFuncAttributeMaxDynamicSharedMemorySize, GSMEM);
    cudaFuncSetAttribute(attn_fused_kernel, cudaFuncAttributeMaxDynamicSharedMemorySize, FA_SMEM);

    embed_kernel<<<BTz, 256>>>(idx, tok_emb, pos_emb);

    const size_t CC  = (size_t)Cz * Cz;
    const size_t C14 = (size_t)Cz * C4z;
    dim3 gQKV(C3z / 128, 16), gCC(Cz / 128, 16), gC4(C4z / 128, 16);
    dim3 gHead((Vz + 127) / 128, 16);

    for (int l = 0; l < Lz; l++) {
        ln_pack_kernel<<<BTz, 256>>>(px, ln1_w + (size_t)l * Cz, ln1_b + (size_t)l * Cz, php);
        gemm_pk_kernel<0, false, true><<<gQKV, 256, GSMEM>>>(
            php, Wq + l * CC, Wk + l * CC, Wv + l * CC,
            bq + (size_t)l * Cz, bk + (size_t)l * Cz, bv + (size_t)l * Cz,
            nullptr, pqkv, nullptr, C3z, Cz);
        attn_fused_kernel<<<dim3(Tz / 64, Bz * Hz), 128, FA_SMEM>>>();
        gemm_pk_kernel<1, false, false><<<gCC, 256, GSMEM>>>(
            pyp, Wo + l * CC, nullptr, nullptr,
            bo + (size_t)l * Cz, nullptr, nullptr, px, px, nullptr, Cz, Cz);
        ln_pack_kernel<<<BTz, 256>>>(px, ln2_w + (size_t)l * Cz, ln2_b + (size_t)l * Cz, php);
        gemm_pk_kernel<2, false, false><<<gC4, 256, GSMEM>>>(
            php, W1 + l * C14, nullptr, nullptr,
            b1 + (size_t)l * C4z, nullptr, nullptr, nullptr, nullptr, pffp, C4z, Cz);
        gemm_pk_kernel<1, false, false><<<gCC, 256, GSMEM>>>(
            pffp, W2 + l * C14, nullptr, nullptr,
            b2 + (size_t)l * Cz, nullptr, nullptr, px, px, nullptr, Cz, C4z);
    }

    ln_pack_kernel<<<BTz, 256>>>(px, lnf_w, lnf_b, php);
    gemm_pk_kernel<3, true, false><<<gHead, 256, GSMEM>>>(
        php, head_w, nullptr, nullptr, nullptr, nullptr, nullptr,
        nullptr, out, nullptr, Vz, Cz);
    loss_row_kernel<<<BTz, 256>>>(out, targets);
    loss_final_kernel<<<1, 256>>>(out, out_size);
}

// round 16
// speedup vs baseline: 1.2905x; 1.1039x over previous
#include <cuda_runtime.h>
#include <cuda_bf16.h>
#include <math.h>
#include <stdint.h>

#define Bz 2
#define Tz 1024
#define Cz 1024
#define Hz 16
#define HDz 64
#define Lz 12
#define Vz 50257
#define BTz (Bz*Tz)
#define C4z (4*Cz)
#define C3z (3*Cz)

// ---------------- scratch (device globals; no allocation) ----------------
__device__ float g_x[BTz*Cz];                         // residual (fp32)
__device__ float g_qkv[(size_t)BTz*C3z];              // QKV output (fp32, attn input)
__device__ float g_red[BTz];
__device__ __nv_bfloat16 g_hp [(size_t)BTz*2*Cz];     // LN output [hi K | lo K]
__device__ __nv_bfloat16 g_yp [(size_t)BTz*2*Cz];     // attn output [hi | lo]
__device__ __nv_bfloat16 g_ffp[(size_t)BTz*2*C4z];    // MLP hidden [hi | lo]

// ---------------- helpers ----------------
__device__ __forceinline__ unsigned short bfhi(float x) {
    return __bfloat16_as_ushort(__float2bfloat16(x));
}
__device__ __forceinline__ unsigned short bflo(float x) {
    __nv_bfloat16 h = __float2bfloat16(x);
    return __bfloat16_as_ushort(__float2bfloat16(x - __bfloat162float(h)));
}

__device__ __forceinline__ float blockReduceSum(float v) {
    __shared__ float sh[33];
    int lane = threadIdx.x & 31, w = threadIdx.x >> 5;
    #pragma unroll
    for (int o = 16; o; o >>= 1) v += __shfl_down_sync(0xffffffffu, v, o);
    __syncthreads();
    if (lane == 0) sh[w] = v;
    __syncthreads();
    if (threadIdx.x == 0) {
        float s = 0.f;
        int nw = blockDim.x >> 5;
        for (int i = 0; i < nw; i++) s += sh[i];
        sh[32] = s;
    }
    __syncthreads();
    return sh[32];
}

__device__ __forceinline__ float blockReduceMax(float v) {
    __shared__ float sh[33];
    int lane = threadIdx.x & 31, w = threadIdx.x >> 5;
    #pragma unroll
    for (int o = 16; o; o >>= 1) v = fmaxf(v, __shfl_down_sync(0xffffffffu, v, o));
    __syncthreads();
    if (lane == 0) sh[w] = v;
    __syncthreads();
    if (threadIdx.x == 0) {
        float s = -1e30f;
        int nw = blockDim.x >> 5;
        for (int i = 0; i < nw; i++) s = fmaxf(s, sh[i]);
        sh[32] = s;
    }
    __syncthreads();
    return sh[32];
}

// ---------------- embedding ----------------
__global__ void embed_kernel(const int* __restrict__ idx,
                             const float* __restrict__ tok,
                             const float* __restrict__ pos) {
    int r = blockIdx.x;
    int c = threadIdx.x * 4;
    int tokid = idx[r];
    float4 te = *(const float4*)(tok + (size_t)tokid * Cz + c);
    float4 pe = *(const float4*)(pos + (size_t)(r % Tz) * Cz + c);
    float4 o;
    o.x = te.x + pe.x; o.y = te.y + pe.y; o.z = te.z + pe.z; o.w = te.w + pe.w;
    *(float4*)(g_x + (size_t)r * Cz + c) = o;
}

// ---------------- layernorm -> packed A rows [hi C | lo C] ----------------
__global__ void ln_pack_kernel(const float* __restrict__ x,
                               const float* __restrict__ w,
                               const float* __restrict__ b,
                               __nv_bfloat16* __restrict__ outp) {
    int r = blockIdx.x;
    const float* xr = x + (size_t)r * Cz;
    float v[4];
    #pragma unroll
    for (int k = 0; k < 4; k++) v[k] = xr[threadIdx.x + k * 256];
    float s = v[0] + v[1] + v[2] + v[3];
    s = blockReduceSum(s);
    float mu = s * (1.0f / Cz);
    float sq = 0.f;
    #pragma unroll
    for (int k = 0; k < 4; k++) { float d = v[k] - mu; sq += d * d; }
    sq = blockReduceSum(sq);
    float rstd = rsqrtf(sq * (1.0f / Cz) + 1e-5f);
    __nv_bfloat16* orow = outp + (size_t)r * 2 * Cz;
    #pragma unroll
    for (int k = 0; k < 4; k++) {
        int c = threadIdx.x + k * 256;
        float xv = (v[k] - mu) * rstd * w[c] + b[c];
        __nv_bfloat16 hb = __float2bfloat16(xv);
        orow[c] = hb;
        orow[Cz + c] = __float2bfloat16(xv - __bfloat162float(hb));
    }
}

// ---------------- mma / ldmatrix primitives ----------------
__device__ __forceinline__ void mma16816(float4& c, uint32_t a0, uint32_t a1,
                                         uint32_t a2, uint32_t a3,
                                         uint32_t b0, uint32_t b1) {
    asm volatile(
        "mma.sync.aligned.m16n8k16.row.col.f32.bf16.bf16.f32 "
        "{%0,%1,%2,%3}, {%4,%5,%6,%7}, {%8,%9}, {%0,%1,%2,%3};"
        : "+f"(c.x), "+f"(c.y), "+f"(c.z), "+f"(c.w)
        : "r"(a0), "r"(a1), "r"(a2), "r"(a3), "r"(b0), "r"(b1));
}

__device__ __forceinline__ void ldsm4(uint32_t& r0, uint32_t& r1,
                                      uint32_t& r2, uint32_t& r3, uint32_t addr) {
    asm volatile("ldmatrix.sync.aligned.m8n8.x4.shared.b16 {%0,%1,%2,%3}, [%4];"
        : "=r"(r0), "=r"(r1), "=r"(r2), "=r"(r3) : "r"(addr));
}

// =========================================================================
// GEMM 128x128 tile, shared-segment hi/lo, 3 MMA passes/kstep.
// 3-buffer ring: PREFA issued BEFORE the barrier is race-free because
// buf (kt+1)%3's last readers (MMAS@kt-2) completed before barrier@kt-1.
// QKV3: B/bias selected per-block from 3 matrices (tile-aligned at 1024).
// EPI: 0=bias->f32, 1=bias+res->f32, 2=bias+gelu->packed[hi|lo], 3=plain->f32
// =========================================================================
#define AST 72
#define ATILEB (128*AST*2)        // 18432 B per side
#define BUFSZ (2*ATILEB)          // 36864 B per stage
#define GSMEM (3*BUFSZ)           // 110592 B (1 CTA/SM)

#define CPA(dst, src) asm volatile("cp.async.cg.shared.global [%0], [%1], 16;\n" :: "r"(dst), "l"(src))

template<int EPI, bool NGUARD, bool QKV3>
__global__ void __launch_bounds__(256, 1)
gemm_pk_kernel(const __nv_bfloat16* __restrict__ Apack,
               const float* __restrict__ Bm0, const float* __restrict__ Bm1,
               const float* __restrict__ Bm2,
               const float* __restrict__ bias0, const float* __restrict__ bias1,
               const float* __restrict__ bias2,
               const float* __restrict__ res,
               float* __restrict__ outF, __nv_bfloat16* __restrict__ outP,
               int N, int K) {
    extern __shared__ __nv_bfloat16 smem[];
    int tid = threadIdx.x, lane = tid & 31, warp = tid >> 5;
    int wm = warp & 1, wn = warp >> 1;
    int g = lane >> 2, tg = lane & 3;
    int rowBlk = blockIdx.y * 128, colBlk = blockIdx.x * 128;
    int row2 = tid >> 1, h2 = tid & 1;          // A staging: 128 rows x {hi,lo}
    int bn = tid & 127, kseg = tid >> 7;        // B staging: 128 cols x 2 k-halves
    int t8 = lane >> 3, r8 = lane & 7;
    int aoff = ((t8 & 1) * 8 + r8) * AST + (t8 >> 1) * 8;
    int boff = ((t8 >> 1) * 8 + r8) * AST + (t8 & 1) * 8;
    uint32_t sbase = (uint32_t)__cvta_generic_to_shared(smem);

    const float* BmS = Bm0;
    const float* biasS = bias0;
    int colLoc = colBlk;
    if (QKV3) {
        int mat = colBlk >> 10;
        BmS   = (mat == 0) ? Bm0   : (mat == 1) ? Bm1   : Bm2;
        biasS = (mat == 0) ? bias0 : (mat == 1) ? bias1 : bias2;
        colLoc = colBlk & 1023;
    }
    const int NB = QKV3 ? Cz : N;

    const __nv_bfloat16* aRow = Apack + (size_t)(rowBlk + row2) * (2 * K) + (size_t)h2 * K;
    int nb = colLoc + bn;
    bool bValid = (!NGUARD) || (nb < N);
    const float* bPtr = BmS + (bValid ? nb : 0);

    float fb[16];
    float4 acc[4][4];
    #pragma unroll
    for (int i = 0; i < 4; i++)
        #pragma unroll
        for (int j = 0; j < 4; j++) acc[i][j] = make_float4(0.f, 0.f, 0.f, 0.f);

#define PREFA(s, kt) { \
        uint32_t ad_ = sbase + (s) * BUFSZ + (uint32_t)(row2 * AST + h2 * 32) * 2; \
        const __nv_bfloat16* sA_ = aRow + (kt) * 32; \
        CPA(ad_, sA_); CPA(ad_ + 16, sA_ + 8); CPA(ad_ + 32, sA_ + 16); CPA(ad_ + 48, sA_ + 24); \
        asm volatile("cp.async.commit_group;\n"); }

#define LDGB(kt) { const float* p = bPtr + (size_t)((kt) * 32 + kseg * 16) * NB; \
        _Pragma("unroll") \
        for (int i = 0; i < 16; i++) fb[i] = (!NGUARD || bValid) ? p[(size_t)i * NB] : 0.f; }

#define CVTB(s) { \
        unsigned short hs_[16], ls_[16]; \
        _Pragma("unroll") \
        for (int i = 0; i < 16; i++) { \
            float x = fb[i]; \
            __nv_bfloat16 h = __float2bfloat16(x); \
            hs_[i] = __bfloat16_as_ushort(h); \
            ls_[i] = __bfloat16_as_ushort(__float2bfloat16(x - __bfloat162float(h))); } \
        __nv_bfloat16* Bs_ = smem + ((s) * BUFSZ + ATILEB) / 2 + bn * AST; \
        uint4* dh = (uint4*)(Bs_ + kseg * 16); \
        dh[0] = ((const uint4*)hs_)[0]; dh[1] = ((const uint4*)hs_)[1]; \
        uint4* dl = (uint4*)(Bs_ + 32 + kseg * 16); \
        dl[0] = ((const uint4*)ls_)[0]; dl[1] = ((const uint4*)ls_)[1]; }

#define MMAS(s) { uint32_t Ab = sbase + (s) * BUFSZ; \
        uint32_t Bb = Ab + ATILEB; \
        _Pragma("unroll") \
        for (int kh = 0; kh < 2; kh++) { \
            int kbh = kh * 16; \
            uint32_t ah[4][4], al[4][4], rbh[4][2], rbl[4][2]; \
            _Pragma("unroll") \
            for (int mf = 0; mf < 4; mf++) { \
                ldsm4(ah[mf][0], ah[mf][1], ah[mf][2], ah[mf][3], \
                      Ab + 2u * (uint32_t)((wm * 64 + mf * 16) * AST + aoff + kbh)); \
                ldsm4(al[mf][0], al[mf][1], al[mf][2], al[mf][3], \
                      Ab + 2u * (uint32_t)((wm * 64 + mf * 16) * AST + aoff + 32 + kbh)); } \
            _Pragma("unroll") \
            for (int p = 0; p < 2; p++) { \
                ldsm4(rbh[2*p][0], rbh[2*p][1], rbh[2*p+1][0], rbh[2*p+1][1], \
                      Bb + 2u * (uint32_t)((wn * 32 + p * 16) * AST + boff + kbh)); \
                ldsm4(rbl[2*p][0], rbl[2*p][1], rbl[2*p+1][0], rbl[2*p+1][1], \
                      Bb + 2u * (uint32_t)((wn * 32 + p * 16) * AST + boff + 32 + kbh)); } \
            _Pragma("unroll") \
            for (int mf = 0; mf < 4; mf++) \
                _Pragma("unroll") \
                for (int nf = 0; nf < 4; nf++) { \
                    mma16816(acc[mf][nf], ah[mf][0], ah[mf][1], ah[mf][2], ah[mf][3], \
                             rbh[nf][0], rbh[nf][1]); \
                    mma16816(acc[mf][nf], al[mf][0], al[mf][1], al[mf][2], al[mf][3], \
                             rbh[nf][0], rbh[nf][1]); \
                    mma16816(acc[mf][nf], ah[mf][0], ah[mf][1], ah[mf][2], ah[mf][3], \
                             rbl[nf][0], rbl[nf][1]); } } }

    int nt = K / 32;
    PREFA(0, 0);
    LDGB(0);
    CVTB(0);
    for (int kt = 0; kt < nt; kt++) {
        int cur = kt % 3;
        int nxt = (kt + 1) % 3;
        if (kt + 1 < nt) {
            LDGB(kt + 1);
            PREFA(nxt, kt + 1);   // pre-barrier: safe (readers of buf nxt done @barrier kt-1)
            asm volatile("cp.async.wait_group 1;\n" ::: "memory");
        } else {
            asm volatile("cp.async.wait_group 0;\n" ::: "memory");
        }
        __syncthreads();
        MMAS(cur);
        if (kt + 1 < nt) CVTB(nxt);
    }

    // ---- epilogue ----
    #pragma unroll
    for (int mf = 0; mf < 4; mf++) {
        int row0 = rowBlk + wm * 64 + mf * 16 + g;
        #pragma unroll
        for (int nf = 0; nf < 4; nf++) {
            int colOff = wn * 32 + nf * 8 + tg * 2;
            int col = colBlk + colOff;
            int colB = colLoc + colOff;
            float vals[4] = {acc[mf][nf].x, acc[mf][nf].y, acc[mf][nf].z, acc[mf][nf].w};
            #pragma unroll
            for (int h = 0; h < 2; h++) {
                int row = row0 + h * 8;
                float v0 = vals[h * 2], v1 = vals[h * 2 + 1];
                if (EPI == 0 || EPI == 1 || EPI == 2) {
                    v0 += biasS[colB]; v1 += biasS[colB + 1];
                }
                if (EPI == 2) {
                    v0 = 0.5f * v0 * (1.0f + erff(v0 * 0.7071067811865476f));
                    v1 = 0.5f * v1 * (1.0f + erff(v1 * 0.7071067811865476f));
                }
                if (EPI == 1) {
                    v0 += res[(size_t)row * N + col];
                    v1 += res[(size_t)row * N + col + 1];
                }
                if (EPI == 2) {
                    size_t rowb = (size_t)row * (size_t)(2 * N);
                    *(uint32_t*)(outP + rowb + col) =
                        (uint32_t)bfhi(v0) | ((uint32_t)bfhi(v1) << 16);
                    *(uint32_t*)(outP + rowb + N + col) =
                        (uint32_t)bflo(v0) | ((uint32_t)bflo(v1) << 16);
                } else {
                    if (!NGUARD || col < N)     outF[(size_t)row * N + col] = v0;
                    if (!NGUARD || col + 1 < N) outF[(size_t)row * N + col + 1] = v1;
                }
            }
        }
    }
#undef PREFA
#undef LDGB
#undef CVTB
#undef MMAS
}

// =========================================================================
// Fused flash attention (epilogue writes g_yp [hi C | lo C]).
// qt reversed so heavy causal tiles are scheduled first.
// =========================================================================
#define FA_QST 200
#define FA_KST 200
#define FA_VST 136
#define FA_SMEM ((64*FA_QST + 64*FA_KST + 64*FA_VST)*2)

__global__ void __launch_bounds__(128, 2)
attn_fused_kernel() {
    extern __shared__ __nv_bfloat16 sm[];
    __nv_bfloat16* Qs = sm;
    __nv_bfloat16* Ks = sm + 64 * FA_QST;
    __nv_bfloat16* Vs = sm + 64 * (FA_QST + FA_KST);
    int tid = threadIdx.x, lane = tid & 31, warp = tid >> 5;
    int qt = gridDim.x - 1 - blockIdx.x;      // heavy blocks first
    int bh = blockIdx.y;
    int b = bh >> 4, h = bh & 15;
    int g = lane >> 2, tg = lane & 3;
    int t8 = lane >> 3, r8 = lane & 7;
    uint32_t sbb = (uint32_t)__cvta_generic_to_shared(sm);
    uint32_t Qb = sbb;
    uint32_t Kb = sbb + 64 * FA_QST * 2;
    uint32_t Vb = sbb + 64 * (FA_QST + FA_KST) * 2;
    int aoff = ((t8 & 1) * 8 + r8) * FA_QST + (t8 >> 1) * 8;
    int koff = ((t8 >> 1) * 8 + r8) * FA_KST + (t8 & 1) * 8;
    int voff = ((t8 >> 1) * 8 + r8) * FA_VST + (t8 & 1) * 8;

    {
        int row = tid >> 1, seg = (tid & 1) * 32;
        const float* src = g_qkv + (size_t)(b * Tz + qt * 64 + row) * C3z + h * HDz + seg;
        uint32_t wbuf[32]; unsigned short hsb[32];
        #pragma unroll
        for (int i = 0; i < 8; i++) {
            float4 v = *(const float4*)(src + i * 4);
            float xs[4] = {v.x, v.y, v.z, v.w};
            #pragma unroll
            for (int e = 0; e < 4; e++) {
                float x = xs[e] * 0.125f;
                __nv_bfloat16 hb = __float2bfloat16(x);
                __nv_bfloat16 lb = __float2bfloat16(x - __bfloat162float(hb));
                int i4 = i * 4 + e;
                wbuf[i4] = (uint32_t)__bfloat16_as_ushort(hb) |
                           ((uint32_t)__bfloat16_as_ushort(lb) << 16);
                hsb[i4] = __bfloat16_as_ushort(hb);
            }
        }
        uint4* d0 = (uint4*)(Qs + row * FA_QST + 2 * seg);
        #pragma unroll
        for (int i = 0; i < 8; i++) d0[i] = ((const uint4*)wbuf)[i];
        uint32_t hw[16];
        #pragma unroll
        for (int j = 0; j < 16; j++)
            hw[j] = (uint32_t)hsb[2 * j] | ((uint32_t)hsb[2 * j + 1] << 16);
        uint4* d1 = (uint4*)(Qs + row * FA_QST + 128 + seg);
        #pragma unroll
        for (int i = 0; i < 4; i++) d1[i] = ((const uint4*)hw)[i];
    }

    float m0 = -1e30f, m1 = -1e30f, l0 = 0.f, l1 = 0.f;
    float4 O[8];
    #pragma unroll
    for (int i = 0; i < 8; i++) O[i] = make_float4(0.f, 0.f, 0.f, 0.f);

    for (int kt = 0; kt <= qt; kt++) {
        {
            int row = tid >> 1, seg = (tid & 1) * 32;
            const float* src = g_qkv + (size_t)(b * Tz + kt * 64 + row) * C3z + Cz + h * HDz + seg;
            uint32_t wbuf[32]; unsigned short lsb[32];
            #pragma unroll
            for (int i = 0; i < 8; i++) {
                float4 v = *(const float4*)(src + i * 4);
                float xs[4] = {v.x, v.y, v.z, v.w};
                #pragma unroll
                for (int e = 0; e < 4; e++) {
                    float x = xs[e];
                    __nv_bfloat16 hb = __float2bfloat16(x);
                    unsigned short hu = __bfloat16_as_ushort(hb);
                    __nv_bfloat16 lb = __float2bfloat16(x - __bfloat162float(hb));
                    int i4 = i * 4 + e;
                    wbuf[i4] = (uint32_t)hu | ((uint32_t)hu << 16);
                    lsb[i4] = __bfloat16_as_ushort(lb);
                }
            }
            uint4* d0 = (uint4*)(Ks + row * FA_KST + 2 * seg);
            #pragma unroll
            for (int i = 0; i < 8; i++) d0[i] = ((const uint4*)wbuf)[i];
            uint32_t lw[16];
            #pragma unroll
            for (int j = 0; j < 16; j++)
                lw[j] = (uint32_t)lsb[2 * j] | ((uint32_t)lsb[2 * j + 1] << 16);
            uint4* d1 = (uint4*)(Ks + row * FA_KST + 128 + seg);
            #pragma unroll
            for (int i = 0; i < 4; i++) d1[i] = ((const uint4*)lw)[i];
        }
        {
            int nd = (tid & 15) * 4;
            int k8 = (tid >> 4) * 8;
            unsigned short vh[4][8], vl[4][8];
            #pragma unroll
            for (int kk = 0; kk < 8; kk++) {
                const float* src = g_qkv + (size_t)(b * Tz + kt * 64 + k8 + kk) * C3z + 2 * Cz + h * HDz + nd;
                float4 v = *(const float4*)src;
                float xs[4] = {v.x, v.y, v.z, v.w};
                #pragma unroll
                for (int e = 0; e < 4; e++) {
                    float x = xs[e];
                    __nv_bfloat16 hb = __float2bfloat16(x);
                    __nv_bfloat16 lb = __float2bfloat16(x - __bfloat162float(hb));
                    vh[e][kk] = __bfloat16_as_ushort(hb);
                    vl[e][kk] = __bfloat16_as_ushort(lb);
                }
            }
            #pragma unroll
            for (int e = 0; e < 4; e++) {
                *(uint4*)(Vs + (nd + e) * FA_VST + k8)      = *(const uint4*)vh[e];
                *(uint4*)(Vs + (nd + e) * FA_VST + 64 + k8) = *(const uint4*)vl[e];
            }
        }
        __syncthreads();

        float4 S[8];
        #pragma unroll
        for (int i = 0; i < 8; i++) S[i] = make_float4(0.f, 0.f, 0.f, 0.f);
        #pragma unroll
        for (int ks = 0; ks < 12; ks++) {
            int kb = ks * 16;
            uint32_t ra0, ra1, ra2, ra3;
            ldsm4(ra0, ra1, ra2, ra3, Qb + 2u * (uint32_t)(warp * 16 * FA_QST + aoff + kb));
            #pragma unroll
            for (int pp = 0; pp < 4; pp++) {
                uint32_t b0, b1, b2, b3;
                ldsm4(b0, b1, b2, b3, Kb + 2u * (uint32_t)((pp * 16) * FA_KST + koff + kb));
                mma16816(S[2 * pp],     ra0, ra1, ra2, ra3, b0, b1);
                mma16816(S[2 * pp + 1], ra0, ra1, ra2, ra3, b2, b3);
            }
        }

        if (kt == qt) {
            int r0 = warp * 16 + g, r1 = r0 + 8;
            #pragma unroll
            for (int j = 0; j < 8; j++) {
                int c0 = j * 8 + 2 * tg, c1 = c0 + 1;
                if (c0 > r0) S[j].x = -1e30f;
                if (c1 > r0) S[j].y = -1e30f;
                if (c0 > r1) S[j].z = -1e30f;
                if (c1 > r1) S[j].w = -1e30f;
            }
        }

        float mx0 = -1e30f, mx1 = -1e30f;
        #pragma unroll
        for (int j = 0; j < 8; j++) {
            mx0 = fmaxf(mx0, fmaxf(S[j].x, S[j].y));
            mx1 = fmaxf(mx1, fmaxf(S[j].z, S[j].w));
        }
        mx0 = fmaxf(mx0, __shfl_xor_sync(0xffffffffu, mx0, 1));
        mx0 = fmaxf(mx0, __shfl_xor_sync(0xffffffffu, mx0, 2));
        mx1 = fmaxf(mx1, __shfl_xor_sync(0xffffffffu, mx1, 1));
        mx1 = fmaxf(mx1, __shfl_xor_sync(0xffffffffu, mx1, 2));
        float mn0 = fmaxf(m0, mx0), mn1 = fmaxf(m1, mx1);
        float al0 = __expf(m0 - mn0), al1 = __expf(m1 - mn1);
        m0 = mn0; m1 = mn1;
        float rs0 = 0.f, rs1 = 0.f;
        #pragma unroll
        for (int j = 0; j < 8; j++) {
            S[j].x = __expf(S[j].x - m0);
            S[j].y = __expf(S[j].y - m0);
            S[j].z = __expf(S[j].z - m1);
            S[j].w = __expf(S[j].w - m1);
            rs0 += S[j].x + S[j].y;
            rs1 += S[j].z + S[j].w;
        }
        rs0 += __shfl_xor_sync(0xffffffffu, rs0, 1);
        rs0 += __shfl_xor_sync(0xffffffffu, rs0, 2);
        rs1 += __shfl_xor_sync(0xffffffffu, rs1, 1);
        rs1 += __shfl_xor_sync(0xffffffffu, rs1, 2);
        l0 = l0 * al0 + rs0;
        l1 = l1 * al1 + rs1;
        #pragma unroll
        for (int j = 0; j < 8; j++) {
            O[j].x *= al0; O[j].y *= al0;
            O[j].z *= al1; O[j].w *= al1;
        }

        #pragma unroll
        for (int kc = 0; kc < 4; kc++) {
            float4 s0 = S[2 * kc], s1 = S[2 * kc + 1];
            float f0[8] = {s0.x, s0.y, s0.z, s0.w, s1.x, s1.y, s1.z, s1.w};
            unsigned short phs[8], pls[8];
            #pragma unroll
            for (int e = 0; e < 8; e++) {
                __nv_bfloat16 hb = __float2bfloat16(f0[e]);
                phs[e] = __bfloat16_as_ushort(hb);
                pls[e] = __bfloat16_as_ushort(__float2bfloat16(f0[e] - __bfloat162float(hb)));
            }
            uint32_t ph0 = (uint32_t)phs[0] | ((uint32_t)phs[1] << 16);
            uint32_t ph1 = (uint32_t)phs[2] | ((uint32_t)phs[3] << 16);
            uint32_t ph2 = (uint32_t)phs[4] | ((uint32_t)phs[5] << 16);
            uint32_t ph3 = (uint32_t)phs[6] | ((uint32_t)phs[7] << 16);
            uint32_t pl0 = (uint32_t)pls[0] | ((uint32_t)pls[1] << 16);
            uint32_t pl1 = (uint32_t)pls[2] | ((uint32_t)pls[3] << 16);
            uint32_t pl2 = (uint32_t)pls[4] | ((uint32_t)pls[5] << 16);
            uint32_t pl3 = (uint32_t)pls[6] | ((uint32_t)pls[7] << 16);

            uint32_t vh[8][2], vl[8][2];
            #pragma unroll
            for (int pp = 0; pp < 4; pp++) {
                ldsm4(vh[2*pp][0], vh[2*pp][1], vh[2*pp+1][0], vh[2*pp+1][1],
                      Vb + 2u * (uint32_t)((pp * 16) * FA_VST + voff + kc * 16));
                ldsm4(vl[2*pp][0], vl[2*pp][1], vl[2*pp+1][0], vl[2*pp+1][1],
                      Vb + 2u * (uint32_t)((pp * 16) * FA_VST + voff + 64 + kc * 16));
            }
            #pragma unroll
            for (int nf = 0; nf < 8; nf++) {
                mma16816(O[nf], ph0, ph1, ph2, ph3, vh[nf][0], vh[nf][1]);
                mma16816(O[nf], pl0, pl1, pl2, pl3, vh[nf][0], vh[nf][1]);
                mma16816(O[nf], ph0, ph1, ph2, ph3, vl[nf][0], vl[nf][1]);
            }
        }
        __syncthreads();
    }

    float i0 = 1.0f / l0, i1 = 1.0f / l1;
    int qrow = qt * 64 + warp * 16 + g;
    size_t rb0 = (size_t)(b * Tz + qrow) * (2 * Cz);
    size_t rb1 = (size_t)(b * Tz + qrow + 8) * (2 * Cz);
    #pragma unroll
    for (int nf = 0; nf < 8; nf++) {
        int colg = h * HDz + nf * 8 + 2 * tg;
        float vx = O[nf].x * i0, vy = O[nf].y * i0;
        float wx = O[nf].z * i1, wy = O[nf].w * i1;
        *(uint32_t*)(g_yp + rb0 + colg)      = (uint32_t)bfhi(vx) | ((uint32_t)bfhi(vy) << 16);
        *(uint32_t*)(g_yp + rb0 + Cz + colg) = (uint32_t)bflo(vx) | ((uint32_t)bflo(vy) << 16);
        *(uint32_t*)(g_yp + rb1 + colg)      = (uint32_t)bfhi(wx) | ((uint32_t)bfhi(wy) << 16);
        *(uint32_t*)(g_yp + rb1 + Cz + colg) = (uint32_t)bflo(wx) | ((uint32_t)bflo(wy) << 16);
    }
}

// ---------------- loss ----------------
__global__ void loss_row_kernel(const float* __restrict__ logits,
                                const int* __restrict__ targets) {
    int r = blockIdx.x;
    const float* row = logits + (size_t)r * Vz;
    int tid = threadIdx.x;
    float mx = -1e30f;
    for (int j = tid; j < Vz; j += 256) mx = fmaxf(mx, row[j]);
    mx = blockReduceMax(mx);
    float s = 0.f;
    for (int j = tid; j < Vz; j += 256) s += expf(row[j] - mx);
    s = blockReduceSum(s);
    if (tid == 0) {
        int t = targets[r];
        g_red[r] = -(row[t] - mx - logf(s));
    }
}

__global__ void loss_final_kernel(float* __restrict__ out, int out_size) {
    int tid = threadIdx.x;
    float s = 0.f;
    for (int j = tid; j < BTz; j += 256) s += g_red[j];
    s = blockReduceSum(s);
    if (tid == 0) {
        long long logits_elems = (long long)BTz * Vz;
        if ((long long)out_size > logits_elems)
            out[logits_elems] = s / (float)BTz;
    }
}

// ---------------- launch ----------------
extern "C" void kernel_launch(void* const* d_in, const int* in_sizes, int n_in,
                              void* d_out, int out_size) {
    const int*   idx     = (const int*)d_in[0];
    const int*   targets = (const int*)d_in[1];
    const float* tok_emb = (const float*)d_in[2];
    const float* pos_emb = (const float*)d_in[3];
    const float* ln1_w   = (const float*)d_in[4];
    const float* ln1_b   = (const float*)d_in[5];
    const float* ln2_w   = (const float*)d_in[6];
    const float* ln2_b   = (const float*)d_in[7];
    const float* Wq = (const float*)d_in[8];
    const float* bq = (const float*)d_in[9];
    const float* Wk = (const float*)d_in[10];
    const float* bk = (const float*)d_in[11];
    const float* Wv = (const float*)d_in[12];
    const float* bv = (const float*)d_in[13];
    const float* Wo = (const float*)d_in[14];
    const float* bo = (const float*)d_in[15];
    const float* W1 = (const float*)d_in[16];
    const float* b1 = (const float*)d_in[17];
    const float* W2 = (const float*)d_in[18];
    const float* b2 = (const float*)d_in[19];
    const float* lnf_w  = (const float*)d_in[20];
    const float* lnf_b  = (const float*)d_in[21];
    const float* head_w = (const float*)d_in[22];
    float* out = (float*)d_out;

    float *px, *pqkv;
    __nv_bfloat16 *php, *pffp, *pyp;
    cudaGetSymbolAddress((void**)&px,   g_x);
    cudaGetSymbolAddress((void**)&pqkv, g_qkv);
    cudaGetSymbolAddress((void**)&php,  g_hp);
    cudaGetSymbolAddress((void**)&pffp, g_ffp);
    cudaGetSymbolAddress((void**)&pyp,  g_yp);

    cudaFuncSetAttribute(gemm_pk_kernel<0, false, true >, cudaFuncAttributeMaxDynamicSharedMemorySize, GSMEM);
    cudaFuncSetAttribute(gemm_pk_kernel<1, false, false>, cudaFuncAttributeMaxDynamicSharedMemorySize, GSMEM);
    cudaFuncSetAttribute(gemm_pk_kernel<2, false, false>, cudaFuncAttributeMaxDynamicSharedMemorySize, GSMEM);
    cudaFuncSetAttribute(gemm_pk_kernel<3, true , false>, cudaFuncAttributeMaxDynamicSharedMemorySize, GSMEM);
    cudaFuncSetAttribute(attn_fused_kernel, cudaFuncAttributeMaxDynamicSharedMemorySize, FA_SMEM);

    embed_kernel<<<BTz, 256>>>(idx, tok_emb, pos_emb);

    const size_t CC  = (size_t)Cz * Cz;
    const size_t C14 = (size_t)Cz * C4z;
    dim3 gQKV(C3z / 128, 16), gCC(Cz / 128, 16), gC4(C4z / 128, 16);
    dim3 gHead((Vz + 127) / 128, 16);

    for (int l = 0; l < Lz; l++) {
        ln_pack_kernel<<<BTz, 256>>>(px, ln1_w + (size_t)l * Cz, ln1_b + (size_t)l * Cz, php);
        gemm_pk_kernel<0, false, true><<<gQKV, 256, GSMEM>>>(
            php, Wq + l * CC, Wk + l * CC, Wv + l * CC,
            bq + (size_t)l * Cz, bk + (size_t)l * Cz, bv + (size_t)l * Cz,
            nullptr, pqkv, nullptr, C3z, Cz);
        attn_fused_kernel<<<dim3(Tz / 64, Bz * Hz), 128, FA_SMEM>>>();
        gemm_pk_kernel<1, false, false><<<gCC, 256, GSMEM>>>(
            pyp, Wo + l * CC, nullptr, nullptr,
            bo + (size_t)l * Cz, nullptr, nullptr, px, px, nullptr, Cz, Cz);
        ln_pack_kernel<<<BTz, 256>>>(px, ln2_w + (size_t)l * Cz, ln2_b + (size_t)l * Cz, php);
        gemm_pk_kernel<2, false, false><<<gC4, 256, GSMEM>>>(
            php, W1 + l * C14, nullptr, nullptr,
            b1 + (size_t)l * C4z, nullptr, nullptr, nullptr, nullptr, pffp, C4z, Cz);
        gemm_pk_kernel<1, false, false><<<gCC, 256, GSMEM>>>(
            pffp, W2 + l * C14, nullptr, nullptr,
            b2 + (size_t)l * Cz, nullptr, nullptr, px, px, nullptr, Cz, C4z);
    }

    ln_pack_kernel<<<BTz, 256>>>(px, lnf_w, lnf_b, php);
    gemm_pk_kernel<3, true, false><<<gHead, 256, GSMEM>>>(
        php, head_w, nullptr, nullptr, nullptr, nullptr, nullptr,
        nullptr, out, nullptr, Vz, Cz);
    loss_row_kernel<<<BTz, 256>>>(out, targets);
    loss_final_kernel<<<1, 256>>>(out, out_size);
}